// round 2
// baseline (speedup 1.0000x reference)
#include <cuda_runtime.h>

#define SEQ   2048
#define DM    768
#define BATCH 4
#define NH    12
#define HD    64
#define ROWS  (BATCH*SEQ)   /* 8192 */
#define ZBN   (BATCH*NH)    /* 48 */

// Scratch (device globals: allocation-free per harness rules)
__device__ float g_q[ROWS*DM];
__device__ float g_k[ROWS*DM];
__device__ float g_v[ROWS*DM];
__device__ float g_o[ROWS*DM];
__device__ float g_S[(long)ZBN*SEQ*SEQ];   // 805 MB
__device__ float g_cm[ZBN*SEQ];
__device__ float g_rs[ZBN*SEQ];

// ---------------------------------------------------------------------------
// Generic K-major SGEMM: C[m,n] = alpha * sum_k A[m,k]*B[n,k] (+bias[n]) (+resid[m,n])
// Optional batching over blockIdx.z with (batch, head) offset decomposition.
// Tile 128x128, BK=16, 256 threads, 8x8 per thread (columns split tx*4 / 64+tx*4).
// ---------------------------------------------------------------------------
__global__ __launch_bounds__(256) void sgemm_kt(
    const float* __restrict__ A, int lda, long sAb, long sAh,
    const float* __restrict__ B, int ldb, long sBb, long sBh,
    float* __restrict__ C, int ldc, long sC,
    int K, int heads, float alpha,
    const float* __restrict__ bias,
    const float* __restrict__ resid)
{
    __shared__ float As[16][132];
    __shared__ float Bs[16][132];

    const int t  = threadIdx.x;
    const int z  = blockIdx.z;
    const int zb = z / heads;
    const int zh = z - zb * heads;
    A += (long)zb * sAb + (long)zh * sAh;
    B += (long)zb * sBb + (long)zh * sBh;
    C += (long)z * sC;

    const int m0 = blockIdx.y << 7;
    const int n0 = blockIdx.x << 7;
    const int arow = t >> 2;
    const int acol = (t & 3) << 2;
    const int ty = t >> 4, tx = t & 15;

    float acc[8][8] = {};

    for (int k0 = 0; k0 < K; k0 += 16) {
#pragma unroll
        for (int i = 0; i < 2; i++) {
            const int r = arow + (i << 6);
            float4 va = *reinterpret_cast<const float4*>(A + (long)(m0 + r) * lda + k0 + acol);
            As[acol    ][r] = va.x;
            As[acol + 1][r] = va.y;
            As[acol + 2][r] = va.z;
            As[acol + 3][r] = va.w;
            float4 vb = *reinterpret_cast<const float4*>(B + (long)(n0 + r) * ldb + k0 + acol);
            Bs[acol    ][r] = vb.x;
            Bs[acol + 1][r] = vb.y;
            Bs[acol + 2][r] = vb.z;
            Bs[acol + 3][r] = vb.w;
        }
        __syncthreads();
#pragma unroll
        for (int kk = 0; kk < 16; kk++) {
            float4 a0 = *reinterpret_cast<const float4*>(&As[kk][ty * 8]);
            float4 a1 = *reinterpret_cast<const float4*>(&As[kk][ty * 8 + 4]);
            float4 b0 = *reinterpret_cast<const float4*>(&Bs[kk][tx * 4]);
            float4 b1 = *reinterpret_cast<const float4*>(&Bs[kk][64 + tx * 4]);
            float a[8] = {a0.x, a0.y, a0.z, a0.w, a1.x, a1.y, a1.z, a1.w};
            float b[8] = {b0.x, b0.y, b0.z, b0.w, b1.x, b1.y, b1.z, b1.w};
#pragma unroll
            for (int i = 0; i < 8; i++)
#pragma unroll
                for (int j = 0; j < 8; j++)
                    acc[i][j] += a[i] * b[j];
        }
        __syncthreads();
    }

#pragma unroll
    for (int i = 0; i < 8; i++) {
        const int m = m0 + ty * 8 + i;
#pragma unroll
        for (int g = 0; g < 2; g++) {
            const int n = n0 + (g << 6) + tx * 4;
            float4 v;
            v.x = acc[i][g * 4 + 0] * alpha;
            v.y = acc[i][g * 4 + 1] * alpha;
            v.z = acc[i][g * 4 + 2] * alpha;
            v.w = acc[i][g * 4 + 3] * alpha;
            if (bias) {
                float4 bf = *reinterpret_cast<const float4*>(bias + n);
                v.x += bf.x; v.y += bf.y; v.z += bf.z; v.w += bf.w;
            }
            if (resid) {
                float4 rf = *reinterpret_cast<const float4*>(resid + (long)m * ldc + n);
                v.x += rf.x; v.y += rf.y; v.z += rf.z; v.w += rf.w;
            }
            *reinterpret_cast<float4*>(C + (long)m * ldc + n) = v;
        }
    }
}

// ---------------------------------------------------------------------------
// Row LayerNorm (no bias), d = 768, in-place, 256 threads per row.
// ---------------------------------------------------------------------------
__global__ __launch_bounds__(256) void ln_kernel(float* __restrict__ xio,
                                                 const float* __restrict__ gamma)
{
    const long row = blockIdx.x;
    float* p = xio + row * DM;
    const int t = threadIdx.x;

    float v0 = p[t], v1 = p[t + 256], v2 = p[t + 512];
    float s  = v0 + v1 + v2;
    float sq = v0 * v0 + v1 * v1 + v2 * v2;

#pragma unroll
    for (int o = 16; o; o >>= 1) {
        s  += __shfl_xor_sync(0xffffffffu, s,  o);
        sq += __shfl_xor_sync(0xffffffffu, sq, o);
    }
    __shared__ float ss[8], sqs[8];
    const int w = t >> 5, ln = t & 31;
    if (ln == 0) { ss[w] = s; sqs[w] = sq; }
    __syncthreads();
    if (w == 0) {
        s  = (ln < 8) ? ss[ln]  : 0.f;
        sq = (ln < 8) ? sqs[ln] : 0.f;
#pragma unroll
        for (int o = 4; o; o >>= 1) {
            s  += __shfl_xor_sync(0xffffffffu, s,  o);
            sq += __shfl_xor_sync(0xffffffffu, sq, o);
        }
        if (ln == 0) { ss[0] = s; sqs[0] = sq; }
    }
    __syncthreads();
    const float mu   = ss[0] * (1.f / DM);
    const float var  = sqs[0] * (1.f / DM) - mu * mu;
    const float rstd = rsqrtf(var + 1e-5f);

    p[t]       = (v0 - mu) * rstd * gamma[t];
    p[t + 256] = (v1 - mu) * rstd * gamma[t + 256];
    p[t + 512] = (v2 - mu) * rstd * gamma[t + 512];
}

// ---------------------------------------------------------------------------
// Column stats for softmax over the QUERY axis: for each (z, k) column,
// max over q and 1/sum_q exp(S - max). Coalesced: thread <-> key column.
// ---------------------------------------------------------------------------
__global__ __launch_bounds__(256) void colstats_kernel(
    const float* __restrict__ S, float* __restrict__ cm, float* __restrict__ rs)
{
    const int z  = blockIdx.y;
    const int kc = (blockIdx.x << 8) + threadIdx.x;
    const float* p = S + (long)z * SEQ * SEQ + kc;

    float m = -1e30f;
    for (int q = 0; q < SEQ; q++) m = fmaxf(m, p[(long)q * SEQ]);
    float s = 0.f;
    for (int q = 0; q < SEQ; q++) s += __expf(p[(long)q * SEQ] - m);

    cm[z * SEQ + kc] = m;
    rs[z * SEQ + kc] = 1.0f / s;
}

// ---------------------------------------------------------------------------
// O = P @ V per (b,h), where P[q,k] = exp(S-colmax[k]) * rcolsum[k] is formed
// on the fly in the smem load. Tile: 128 q x 64 hd, BK=32 keys.
// Writes directly to merged (b, l, h*hd) layout.
// ---------------------------------------------------------------------------
__global__ __launch_bounds__(256) void pv_kernel(
    const float* __restrict__ S, const float* __restrict__ V,
    const float* __restrict__ cm, const float* __restrict__ rs,
    float* __restrict__ O)
{
    __shared__ float Ps[32][132];
    __shared__ float Vs[32][68];

    const int z = blockIdx.y;
    const int b = z / NH, h = z - b * NH;
    const int q0 = blockIdx.x << 7;
    const float* Sp  = S  + (long)z * SEQ * SEQ;
    const float* cmz = cm + z * SEQ;
    const float* rsz = rs + z * SEQ;
    const float* Vp  = V  + (long)b * SEQ * DM + h * HD;

    const int t  = threadIdx.x;
    const int ty = t >> 4, tx = t & 15;
    float acc[8][4] = {};

    for (int k0 = 0; k0 < SEQ; k0 += 32) {
#pragma unroll
        for (int i = 0; i < 4; i++) {
            const int idx = t + (i << 8);
            const int r = idx >> 3;
            const int c = (idx & 7) << 2;
            float4 sv = *reinterpret_cast<const float4*>(Sp + (long)(q0 + r) * SEQ + k0 + c);
            float4 m4 = *reinterpret_cast<const float4*>(cmz + k0 + c);
            float4 r4 = *reinterpret_cast<const float4*>(rsz + k0 + c);
            Ps[c    ][r] = __expf(sv.x - m4.x) * r4.x;
            Ps[c + 1][r] = __expf(sv.y - m4.y) * r4.y;
            Ps[c + 2][r] = __expf(sv.z - m4.z) * r4.z;
            Ps[c + 3][r] = __expf(sv.w - m4.w) * r4.w;
        }
#pragma unroll
        for (int i = 0; i < 2; i++) {
            const int idx = t + (i << 8);
            const int r = idx >> 4;
            const int c = (idx & 15) << 2;
            *reinterpret_cast<float4*>(&Vs[r][c]) =
                *reinterpret_cast<const float4*>(Vp + (long)(k0 + r) * DM + c);
        }
        __syncthreads();
#pragma unroll
        for (int kk = 0; kk < 32; kk++) {
            float4 a0 = *reinterpret_cast<const float4*>(&Ps[kk][ty * 8]);
            float4 a1 = *reinterpret_cast<const float4*>(&Ps[kk][ty * 8 + 4]);
            float4 bv = *reinterpret_cast<const float4*>(&Vs[kk][tx * 4]);
            float a[8] = {a0.x, a0.y, a0.z, a0.w, a1.x, a1.y, a1.z, a1.w};
#pragma unroll
            for (int i = 0; i < 8; i++) {
                acc[i][0] += a[i] * bv.x;
                acc[i][1] += a[i] * bv.y;
                acc[i][2] += a[i] * bv.z;
                acc[i][3] += a[i] * bv.w;
            }
        }
        __syncthreads();
    }

#pragma unroll
    for (int i = 0; i < 8; i++) {
        const long m = (long)(b * SEQ + q0 + ty * 8 + i);
        float4 v = {acc[i][0], acc[i][1], acc[i][2], acc[i][3]};
        *reinterpret_cast<float4*>(O + m * DM + h * HD + tx * 4) = v;
    }
}

// ---------------------------------------------------------------------------
extern "C" void kernel_launch(void* const* d_in, const int* in_sizes, int n_in,
                              void* d_out, int out_size)
{
    const float* x  = (const float*)d_in[0];
    const float* Wq = (const float*)d_in[1];
    const float* Wk = (const float*)d_in[2];
    const float* bk = (const float*)d_in[3];
    const float* Wv = (const float*)d_in[4];
    const float* bv = (const float*)d_in[5];
    const float* gq = (const float*)d_in[6];
    const float* gk = (const float*)d_in[7];
    const float* Wo = (const float*)d_in[8];
    const float* bo = (const float*)d_in[9];
    float* out = (float*)d_out;

    float *q, *k, *v, *o, *S, *cm, *rs;
    cudaGetSymbolAddress((void**)&q,  g_q);
    cudaGetSymbolAddress((void**)&k,  g_k);
    cudaGetSymbolAddress((void**)&v,  g_v);
    cudaGetSymbolAddress((void**)&o,  g_o);
    cudaGetSymbolAddress((void**)&S,  g_S);
    cudaGetSymbolAddress((void**)&cm, g_cm);
    cudaGetSymbolAddress((void**)&rs, g_rs);

    const dim3 blk(256);
    const dim3 gproj(DM / 128, ROWS / 128, 1);

    // Projections: q = x Wq^T, k = x Wk^T + bk, v = x Wv^T + bv
    sgemm_kt<<<gproj, blk>>>(x, DM, 0, 0, Wq, DM, 0, 0, q, DM, 0, DM, 1, 1.f, nullptr, nullptr);
    sgemm_kt<<<gproj, blk>>>(x, DM, 0, 0, Wk, DM, 0, 0, k, DM, 0, DM, 1, 1.f, bk,      nullptr);
    sgemm_kt<<<gproj, blk>>>(x, DM, 0, 0, Wv, DM, 0, 0, v, DM, 0, DM, 1, 1.f, bv,      nullptr);

    // QK-norm over full dmodel
    ln_kernel<<<ROWS, blk>>>(q, gq);
    ln_kernel<<<ROWS, blk>>>(k, gk);

    // Scores: S[z,q,k] = 0.125 * <q_head, k_head>, batched over z = b*12 + h
    const dim3 gs(SEQ / 128, SEQ / 128, ZBN);
    sgemm_kt<<<gs, blk>>>(q, DM, (long)SEQ * DM, HD,
                          k, DM, (long)SEQ * DM, HD,
                          S, SEQ, (long)SEQ * SEQ,
                          HD, NH, 0.125f, nullptr, nullptr);

    // Per-key-column softmax stats (softmax over query axis)
    colstats_kernel<<<dim3(SEQ / 256, ZBN), blk>>>(S, cm, rs);

    // O = softmax_q(S) @ V, merged-head layout
    pv_kernel<<<dim3(SEQ / 128, ZBN), blk>>>(S, v, cm, rs, o);

    // out = O @ Wo^T + bo + x
    sgemm_kt<<<gproj, blk>>>(o, DM, 0, 0, Wo, DM, 0, 0, out, DM, 0, DM, 1, 1.f, bo, x);
}

// round 5
// speedup vs baseline: 1.7497x; 1.7497x over previous
#include <cuda_runtime.h>
#include <cuda_bf16.h>
#include <cstdint>

#define SEQ 2048
#define DM 768
#define NH 12
#define HD 64
#define ROWS 8192
#define ZBN 48
typedef __nv_bfloat16 bf16;

// ---------------- scratch ----------------
__device__ __align__(16) bf16 g_xh[ROWS*DM], g_xl[ROWS*DM];
__device__ __align__(16) bf16 g_wh[4][DM*DM], g_wl[4][DM*DM];
__device__ __align__(16) float g_q[ROWS*DM], g_k[ROWS*DM], g_v[ROWS*DM];
__device__ __align__(16) bf16 g_qh[ROWS*DM], g_ql[ROWS*DM], g_kh[ROWS*DM], g_kl[ROWS*DM];
__device__ __align__(16) bf16 g_vth[(long)ZBN*HD*SEQ], g_vtl[(long)ZBN*HD*SEQ];
__device__ __align__(16) float g_S[(long)ZBN*SEQ*SEQ];
__device__ __align__(16) float g_coef[ZBN*SEQ];
__device__ __align__(16) bf16 g_oh[ROWS*DM], g_ol[ROWS*DM];

#define SWZ(o) ((o)^(((o)>>3)&0x70))

__device__ __forceinline__ uint32_t smem_u32(const void* p){
    uint32_t a; asm("{ .reg .u64 t; cvta.to.shared.u64 t, %1; cvt.u32.u64 %0, t; }":"=r"(a):"l"(p)); return a;
}
__device__ __forceinline__ void split2(float a,float b,unsigned&hp,unsigned&lp){
    __nv_bfloat162 h=__floats2bfloat162_rn(a,b); float2 hf=__bfloat1622float2(h);
    __nv_bfloat162 l=__floats2bfloat162_rn(a-hf.x,b-hf.y);
    hp=*reinterpret_cast<unsigned*>(&h); lp=*reinterpret_cast<unsigned*>(&l);
}
// ldmatrix x4: lanes 0-31 -> row = row0+(lane&15), 16B chunk sel = lane>>4
__device__ __forceinline__ void ldm4(uint32_t* r, uint32_t base, int row0, int ks, int lane){
    uint32_t addr = base + SWZ((unsigned)((row0+(lane&15))<<7) + (unsigned)(((ks<<1)+(lane>>4))<<4));
    asm volatile("ldmatrix.sync.aligned.m8n8.x4.shared.b16 {%0,%1,%2,%3}, [%4];"
        :"=r"(r[0]),"=r"(r[1]),"=r"(r[2]),"=r"(r[3]):"r"(addr));
}
__device__ __forceinline__ void mma16816(float* d, const uint32_t* a, uint32_t b0, uint32_t b1){
    asm volatile("mma.sync.aligned.m16n8k16.row.col.f32.bf16.bf16.f32 "
        "{%0,%1,%2,%3},{%4,%5,%6,%7},{%8,%9},{%0,%1,%2,%3};"
        : "+f"(d[0]),"+f"(d[1]),"+f"(d[2]),"+f"(d[3])
        : "r"(a[0]),"r"(a[1]),"r"(a[2]),"r"(a[3]),"r"(b0),"r"(b1));
}
// fill ROWSN x 64 bf16 tile (hi+lo) into SW128-swizzled smem
template<int ROWSN>
__device__ __forceinline__ void fill_pair(char* sh, char* sl,
    const bf16* __restrict__ gh, const bf16* __restrict__ gl, int ldK, int tid){
#pragma unroll
    for(int i=0;i<ROWSN/32;i++){
        int idx=tid+(i<<8); int r=idx>>3, c=idx&7;
        long g=(long)r*ldK + (c<<3);
        unsigned sw=SWZ((unsigned)((r<<7)+(c<<4)));
        *reinterpret_cast<uint4*>(sh+sw)=*reinterpret_cast<const uint4*>(gh+g);
        *reinterpret_cast<uint4*>(sl+sw)=*reinterpret_cast<const uint4*>(gl+g);
    }
}

// ---- fp32 -> split bf16 ----
__global__ __launch_bounds__(256) void split_k(const float* __restrict__ in, bf16* __restrict__ oh, bf16* __restrict__ ol, long n){
    long i=((long)blockIdx.x*256+threadIdx.x)*4;
    if(i>=n) return;
    float4 v=*reinterpret_cast<const float4*>(in+i);
    unsigned h01,l01,h23,l23; split2(v.x,v.y,h01,l01); split2(v.z,v.w,h23,l23);
    *reinterpret_cast<uint2*>(oh+i)=make_uint2(h01,h23);
    *reinterpret_cast<uint2*>(ol+i)=make_uint2(l01,l23);
}

// ---------------------------------------------------------------------------
// Generic split-bf16 mma.sync GEMM: C[m,n] = sum_k A[m,k]B[n,k] (+bias)(+resid)
// Tile 128x128, BK=64, 256 threads (8 warps, 4m x 2n), warp tile 32x64.
// Batched over blockIdx.z with (batch,head) decomposition for scores.
// ---------------------------------------------------------------------------
__global__ __launch_bounds__(256) void gemm_mma(
    const bf16* __restrict__ ah,const bf16* __restrict__ al,
    const bf16* __restrict__ bh,const bf16* __restrict__ bl,
    const float* __restrict__ bias,const float* __restrict__ resid,
    float* __restrict__ C,
    int K,int lda,int ldb,int N,
    int nh,long aB,long aH,long bB,long bH,long cZ)
{
    extern __shared__ char smem[];
    const uint32_t sb=smem_u32(smem);
    const uint32_t sAh=sb, sAl=sb+16384, sBh=sb+32768, sBl=sb+49152;
    const int tid=threadIdx.x, wid=tid>>5, lane=tid&31;
    const int m0=blockIdx.y<<7, n0=blockIdx.x<<7;
    const int wm=(wid&3)<<5, wn=(wid>>2)<<6;
    const int z=blockIdx.z, zb=z/nh, zh=z-zb*nh;
    const bf16* Ah=ah+zb*aB+zh*aH+(long)m0*lda;
    const bf16* Al=al+zb*aB+zh*aH+(long)m0*lda;
    const bf16* Bh=bh+zb*bB+zh*bH+(long)n0*ldb;
    const bf16* Bl=bl+zb*bB+zh*bH+(long)n0*ldb;
    C += z*cZ;

    float acc[2][8][4]={};
    for(int k0=0;k0<K;k0+=64){
        fill_pair<128>(smem,       smem+16384, Ah+k0, Al+k0, lda, tid);
        fill_pair<128>(smem+32768, smem+49152, Bh+k0, Bl+k0, ldb, tid);
        __syncthreads();
#pragma unroll
        for(int ks=0;ks<4;ks++){
            uint32_t a_h[2][4], a_l[2][4];
            ldm4(a_h[0], sAh, wm,    ks, lane); ldm4(a_h[1], sAh, wm+16, ks, lane);
            ldm4(a_l[0], sAl, wm,    ks, lane); ldm4(a_l[1], sAl, wm+16, ks, lane);
            uint32_t b_h[4][4], b_l[4][4];
#pragma unroll
            for(int j=0;j<4;j++){
                ldm4(b_h[j], sBh, wn+(j<<4), ks, lane);
                ldm4(b_l[j], sBl, wn+(j<<4), ks, lane);
            }
#pragma unroll
            for(int mi=0;mi<2;mi++)
#pragma unroll
                for(int j=0;j<4;j++){
                    mma16816(acc[mi][2*j],   a_h[mi], b_h[j][0], b_h[j][2]);
                    mma16816(acc[mi][2*j+1], a_h[mi], b_h[j][1], b_h[j][3]);
                    mma16816(acc[mi][2*j],   a_h[mi], b_l[j][0], b_l[j][2]);
                    mma16816(acc[mi][2*j+1], a_h[mi], b_l[j][1], b_l[j][3]);
                    mma16816(acc[mi][2*j],   a_l[mi], b_h[j][0], b_h[j][2]);
                    mma16816(acc[mi][2*j+1], a_l[mi], b_h[j][1], b_h[j][3]);
                }
        }
        __syncthreads();
    }
#pragma unroll
    for(int mi=0;mi<2;mi++)
#pragma unroll
        for(int j=0;j<4;j++)
#pragma unroll
            for(int sub=0;sub<2;sub++){
                float* d=acc[mi][2*j+sub];
                int col=n0+wn+(j<<4)+(sub<<3)+((lane&3)<<1);
                long row=m0+wm+(mi<<4)+(lane>>2);
                float2 v0=make_float2(d[0],d[1]), v1=make_float2(d[2],d[3]);
                if(bias){
                    float2 bv=*reinterpret_cast<const float2*>(bias+col);
                    v0.x+=bv.x; v0.y+=bv.y; v1.x+=bv.x; v1.y+=bv.y;
                }
                if(resid){
                    float2 r0=*reinterpret_cast<const float2*>(resid+row*N+col);
                    float2 r1=*reinterpret_cast<const float2*>(resid+(row+8)*N+col);
                    v0.x+=r0.x; v0.y+=r0.y; v1.x+=r1.x; v1.y+=r1.y;
                }
                *reinterpret_cast<float2*>(C+row*N+col)=v0;
                *reinterpret_cast<float2*>(C+(row+8)*N+col)=v1;
            }
}

// ---- LN (no bias) -> split bf16, scale folded ----
__global__ __launch_bounds__(256) void ln2bf(const float* __restrict__ in,const float* __restrict__ gamma,float scale,
                                             bf16* __restrict__ oh,bf16* __restrict__ ol){
    const long row=blockIdx.x; const float* p=in+row*DM; const int t=threadIdx.x;
    float v0=p[t],v1=p[t+256],v2=p[t+512];
    float s=v0+v1+v2, sq=v0*v0+v1*v1+v2*v2;
#pragma unroll
    for(int o=16;o;o>>=1){ s+=__shfl_xor_sync(~0u,s,o); sq+=__shfl_xor_sync(~0u,sq,o); }
    __shared__ float ss[8],sqs[8];
    int w=t>>5,ln=t&31;
    if(ln==0){ss[w]=s;sqs[w]=sq;} __syncthreads();
    if(w==0){ s=(ln<8)?ss[ln]:0.f; sq=(ln<8)?sqs[ln]:0.f;
#pragma unroll
        for(int o=4;o;o>>=1){ s+=__shfl_xor_sync(~0u,s,o); sq+=__shfl_xor_sync(~0u,sq,o); }
        if(ln==0){ss[0]=s;sqs[0]=sq;} }
    __syncthreads();
    float mu=ss[0]*(1.f/DM), var=sqs[0]*(1.f/DM)-mu*mu, rstd=rsqrtf(var+1e-5f)*scale;
#pragma unroll
    for(int g=0;g<3;g++){
        int c=t+g*256; float y=((g==0?v0:g==1?v1:v2)-mu)*rstd*gamma[c];
        bf16 h=__float2bfloat16(y); oh[row*DM+c]=h; ol[row*DM+c]=__float2bfloat16(y-__bfloat162float(h));
    }
}

// ---- v [8192][768] -> vt split [z][64][2048] ----
__global__ void vtrans(const float* __restrict__ v, bf16* __restrict__ vth, bf16* __restrict__ vtl){
    __shared__ float tile[32][33];
    int b=blockIdx.z, c0=blockIdx.y*32, t0=blockIdx.x*32;
    int tx=threadIdx.x, ty=threadIdx.y;
#pragma unroll
    for(int j=0;j<32;j+=8) tile[ty+j][tx]=v[(long)(b*SEQ+t0+ty+j)*DM+c0+tx];
    __syncthreads();
    int z=b*NH+(c0>>6), ch=c0&63;
#pragma unroll
    for(int j=0;j<32;j+=8){
        float val=tile[tx][ty+j];
        bf16 h=__float2bfloat16(val);
        long o=((long)z*HD+ch+ty+j)*SEQ+t0+tx;
        vth[o]=h; vtl[o]=__float2bfloat16(val-__bfloat162float(h));
    }
}

// ---- per key column: coef = max_q + log(sum_q exp(s-max)) ----
__global__ __launch_bounds__(256) void colstats(const float* __restrict__ S, float* __restrict__ coef){
    const int z=blockIdx.y, k=(blockIdx.x<<8)+threadIdx.x;
    const float* p=S+(long)z*SEQ*SEQ+k;
    float m=-1e30f, s=0.f;
    for(int q=0;q<SEQ;q++){
        float x=p[(long)q*SEQ];
        if(x<=m) s+=__expf(x-m);
        else { s=s*__expf(m-x)+1.f; m=x; }
    }
    coef[z*SEQ+k]=m+__logf(s);
}

// ---------------------------------------------------------------------------
// PV: O[b*SEQ+q][h*64+c] = sum_k exp(S[z][q][k]-coef[z][k]) * VT[z][c][k]
// Tile 128(q) x 64(hd), BK=64; A built on the fly with exp+split; out split bf16.
// ---------------------------------------------------------------------------
__global__ __launch_bounds__(256) void pv_mma(
    const float* __restrict__ S,const float* __restrict__ coef,
    const bf16* __restrict__ vth,const bf16* __restrict__ vtl,
    bf16* __restrict__ oh, bf16* __restrict__ ol)
{
    extern __shared__ char smem[];
    const uint32_t sb=smem_u32(smem);
    const uint32_t sAh=sb, sAl=sb+16384, sBh=sb+32768, sBl=sb+40960;
    const int tid=threadIdx.x, wid=tid>>5, lane=tid&31;
    const int z=blockIdx.y, b=z/NH, h=z-b*NH;
    const int q0=blockIdx.x<<7;
    const int wm=(wid&3)<<5, wn=(wid>>2)<<5;
    const float* Sz=S+(long)z*SEQ*SEQ;
    const float* cz=coef+(long)z*SEQ;
    const bf16* Vh=vth+(long)z*HD*SEQ;
    const bf16* Vl=vtl+(long)z*HD*SEQ;

    float acc[2][4][4]={};
    for(int k0=0;k0<SEQ;k0+=64){
#pragma unroll
        for(int i=0;i<8;i++){
            int idx=tid+(i<<8); int r=idx>>4, c4=idx&15;
            float4 v=*reinterpret_cast<const float4*>(Sz+(long)(q0+r)*SEQ+k0+(c4<<2));
            float4 cf=*reinterpret_cast<const float4*>(cz+k0+(c4<<2));
            float p0=__expf(v.x-cf.x),p1=__expf(v.y-cf.y),p2=__expf(v.z-cf.z),p3=__expf(v.w-cf.w);
            unsigned h01,l01,h23,l23; split2(p0,p1,h01,l01); split2(p2,p3,h23,l23);
            unsigned sw=SWZ((unsigned)((r<<7)+((c4>>1)<<4)))+((c4&1)<<3);
            *reinterpret_cast<uint2*>(smem+sw)=make_uint2(h01,h23);
            *reinterpret_cast<uint2*>(smem+16384+sw)=make_uint2(l01,l23);
        }
        fill_pair<64>(smem+32768, smem+40960, Vh+k0, Vl+k0, SEQ, tid);
        __syncthreads();
#pragma unroll
        for(int ks=0;ks<4;ks++){
            uint32_t a_h[2][4], a_l[2][4];
            ldm4(a_h[0], sAh, wm,    ks, lane); ldm4(a_h[1], sAh, wm+16, ks, lane);
            ldm4(a_l[0], sAl, wm,    ks, lane); ldm4(a_l[1], sAl, wm+16, ks, lane);
            uint32_t b_h[2][4], b_l[2][4];
#pragma unroll
            for(int j=0;j<2;j++){
                ldm4(b_h[j], sBh, wn+(j<<4), ks, lane);
                ldm4(b_l[j], sBl, wn+(j<<4), ks, lane);
            }
#pragma unroll
            for(int mi=0;mi<2;mi++)
#pragma unroll
                for(int j=0;j<2;j++){
                    mma16816(acc[mi][2*j],   a_h[mi], b_h[j][0], b_h[j][2]);
                    mma16816(acc[mi][2*j+1], a_h[mi], b_h[j][1], b_h[j][3]);
                    mma16816(acc[mi][2*j],   a_h[mi], b_l[j][0], b_l[j][2]);
                    mma16816(acc[mi][2*j+1], a_h[mi], b_l[j][1], b_l[j][3]);
                    mma16816(acc[mi][2*j],   a_l[mi], b_h[j][0], b_h[j][2]);
                    mma16816(acc[mi][2*j+1], a_l[mi], b_h[j][1], b_h[j][3]);
                }
        }
        __syncthreads();
    }
#pragma unroll
    for(int mi=0;mi<2;mi++)
#pragma unroll
        for(int j=0;j<2;j++)
#pragma unroll
            for(int sub=0;sub<2;sub++){
                float* d=acc[mi][2*j+sub];
                int col=h*HD+wn+(j<<4)+(sub<<3)+((lane&3)<<1);
                long row=(long)b*SEQ+q0+wm+(mi<<4)+(lane>>2);
                unsigned hp,lp;
                split2(d[0],d[1],hp,lp);
                *reinterpret_cast<unsigned*>(oh+row*DM+col)=hp;
                *reinterpret_cast<unsigned*>(ol+row*DM+col)=lp;
                split2(d[2],d[3],hp,lp);
                *reinterpret_cast<unsigned*>(oh+(row+8)*DM+col)=hp;
                *reinterpret_cast<unsigned*>(ol+(row+8)*DM+col)=lp;
            }
}

extern "C" void kernel_launch(void* const* d_in, const int* in_sizes, int n_in,
                              void* d_out, int out_size)
{
    const float* x =(const float*)d_in[0];
    const float* Wq=(const float*)d_in[1];
    const float* Wk=(const float*)d_in[2];
    const float* bk=(const float*)d_in[3];
    const float* Wv=(const float*)d_in[4];
    const float* bv=(const float*)d_in[5];
    const float* gq=(const float*)d_in[6];
    const float* gk=(const float*)d_in[7];
    const float* Wo=(const float*)d_in[8];
    const float* bo=(const float*)d_in[9];
    float* out=(float*)d_out;

    bf16 *xh,*xl,*wh,*wl,*qh,*ql,*kh,*kl,*vth,*vtl,*oh,*ol;
    float *q,*k,*v,*S,*coef;
    cudaGetSymbolAddress((void**)&xh,g_xh); cudaGetSymbolAddress((void**)&xl,g_xl);
    cudaGetSymbolAddress((void**)&wh,g_wh); cudaGetSymbolAddress((void**)&wl,g_wl);
    cudaGetSymbolAddress((void**)&q,g_q); cudaGetSymbolAddress((void**)&k,g_k);
    cudaGetSymbolAddress((void**)&v,g_v);
    cudaGetSymbolAddress((void**)&qh,g_qh); cudaGetSymbolAddress((void**)&ql,g_ql);
    cudaGetSymbolAddress((void**)&kh,g_kh); cudaGetSymbolAddress((void**)&kl,g_kl);
    cudaGetSymbolAddress((void**)&vth,g_vth); cudaGetSymbolAddress((void**)&vtl,g_vtl);
    cudaGetSymbolAddress((void**)&S,g_S); cudaGetSymbolAddress((void**)&coef,g_coef);
    cudaGetSymbolAddress((void**)&oh,g_oh); cudaGetSymbolAddress((void**)&ol,g_ol);

    cudaFuncSetAttribute(gemm_mma, cudaFuncAttributeMaxDynamicSharedMemorySize, 65536);
    cudaFuncSetAttribute(pv_mma,   cudaFuncAttributeMaxDynamicSharedMemorySize, 49152);

    const long NX=(long)ROWS*DM, NW=(long)DM*DM;
    split_k<<<NX/1024,256>>>(x, xh, xl, NX);
    split_k<<<NW/1024,256>>>(Wq, wh+0*NW, wl+0*NW, NW);
    split_k<<<NW/1024,256>>>(Wk, wh+1*NW, wl+1*NW, NW);
    split_k<<<NW/1024,256>>>(Wv, wh+2*NW, wl+2*NW, NW);
    split_k<<<NW/1024,256>>>(Wo, wh+3*NW, wl+3*NW, NW);

    dim3 gp(DM/128, ROWS/128, 1);
    gemm_mma<<<gp,256,65536>>>(xh,xl, wh+0*NW,wl+0*NW, nullptr, nullptr, q, DM, DM, DM, DM, 1,0,0,0,0,0);
    gemm_mma<<<gp,256,65536>>>(xh,xl, wh+1*NW,wl+1*NW, bk,      nullptr, k, DM, DM, DM, DM, 1,0,0,0,0,0);
    gemm_mma<<<gp,256,65536>>>(xh,xl, wh+2*NW,wl+2*NW, bv,      nullptr, v, DM, DM, DM, DM, 1,0,0,0,0,0);

    ln2bf<<<ROWS,256>>>(q, gq, 0.125f, qh, ql);
    ln2bf<<<ROWS,256>>>(k, gk, 1.0f,   kh, kl);

    vtrans<<<dim3(SEQ/32, DM/32, 4), dim3(32,8)>>>(v, vth, vtl);

    // scores: S[z][q][k], A=q slice, B=k slice, K=64 (one slab)
    gemm_mma<<<dim3(SEQ/128, SEQ/128, ZBN),256,65536>>>(
        qh,ql, kh,kl, nullptr, nullptr, S,
        HD, DM, DM, SEQ,
        NH, (long)SEQ*DM, HD, (long)SEQ*DM, HD, (long)SEQ*SEQ);

    colstats<<<dim3(SEQ/256, ZBN),256>>>(S, coef);

    pv_mma<<<dim3(SEQ/128, ZBN),256,49152>>>(S, coef, vth, vtl, oh, ol);

    gemm_mma<<<gp,256,65536>>>(oh,ol, wh+3*NW,wl+3*NW, bo, x, out, DM, DM, DM, DM, 1,0,0,0,0,0);
}

// round 6
// speedup vs baseline: 2.1074x; 1.2044x over previous
#include <cuda_runtime.h>
#include <cuda_bf16.h>
#include <cstdint>

#define SEQ 2048
#define DM 768
#define NH 12
#define HD 64
#define ROWS 8192
#define ZBN 48
typedef __nv_bfloat16 bf16;

// ---------------- scratch ----------------
__device__ __align__(16) bf16 g_xh[ROWS*DM], g_xl[ROWS*DM];
__device__ __align__(16) bf16 g_wh[4][DM*DM], g_wl[4][DM*DM];
__device__ __align__(16) float g_q[ROWS*DM], g_k[ROWS*DM], g_v[ROWS*DM];
__device__ __align__(16) bf16 g_qh[ROWS*DM], g_ql[ROWS*DM], g_kh[ROWS*DM], g_kl[ROWS*DM];
__device__ __align__(16) bf16 g_vth[(long)ZBN*HD*SEQ], g_vtl[(long)ZBN*HD*SEQ];
__device__ __align__(16) bf16 g_eh[(long)ZBN*SEQ*SEQ], g_el[(long)ZBN*SEQ*SEQ];
__device__ __align__(16) float g_psum[(long)ZBN*16*SEQ];
__device__ __align__(16) float g_rsum[ZBN*SEQ];
__device__ __align__(16) bf16 g_oh[ROWS*DM], g_ol[ROWS*DM];

#define SWZ(o) ((o)^(((o)>>3)&0x70))

__device__ __forceinline__ uint32_t smem_u32(const void* p){
    uint32_t a; asm("{ .reg .u64 t; cvta.to.shared.u64 t, %1; cvt.u32.u64 %0, t; }":"=r"(a):"l"(p)); return a;
}
__device__ __forceinline__ void split2(float a,float b,unsigned&hp,unsigned&lp){
    __nv_bfloat162 h=__floats2bfloat162_rn(a,b); float2 hf=__bfloat1622float2(h);
    __nv_bfloat162 l=__floats2bfloat162_rn(a-hf.x,b-hf.y);
    hp=*reinterpret_cast<unsigned*>(&h); lp=*reinterpret_cast<unsigned*>(&l);
}
__device__ __forceinline__ void ldm4(uint32_t* r, uint32_t base, int row0, int ks, int lane){
    uint32_t addr = base + SWZ((unsigned)((row0+(lane&15))<<7) + (unsigned)(((ks<<1)+(lane>>4))<<4));
    asm volatile("ldmatrix.sync.aligned.m8n8.x4.shared.b16 {%0,%1,%2,%3}, [%4];"
        :"=r"(r[0]),"=r"(r[1]),"=r"(r[2]),"=r"(r[3]):"r"(addr));
}
__device__ __forceinline__ void mma16816(float* d, const uint32_t* a, uint32_t b0, uint32_t b1){
    asm volatile("mma.sync.aligned.m16n8k16.row.col.f32.bf16.bf16.f32 "
        "{%0,%1,%2,%3},{%4,%5,%6,%7},{%8,%9},{%0,%1,%2,%3};"
        : "+f"(d[0]),"+f"(d[1]),"+f"(d[2]),"+f"(d[3])
        : "r"(a[0]),"r"(a[1]),"r"(a[2]),"r"(a[3]),"r"(b0),"r"(b1));
}
template<int ROWSN>
__device__ __forceinline__ void fill_pair(char* sh, char* sl,
    const bf16* __restrict__ gh, const bf16* __restrict__ gl, int ldK, int tid){
#pragma unroll
    for(int i=0;i<ROWSN/32;i++){
        int idx=tid+(i<<8); int r=idx>>3, c=idx&7;
        long g=(long)r*ldK + (c<<3);
        unsigned sw=SWZ((unsigned)((r<<7)+(c<<4)));
        *reinterpret_cast<uint4*>(sh+sw)=*reinterpret_cast<const uint4*>(gh+g);
        *reinterpret_cast<uint4*>(sl+sw)=*reinterpret_cast<const uint4*>(gl+g);
    }
}

// ---- fp32 -> split bf16 ----
__global__ __launch_bounds__(256) void split_k(const float* __restrict__ in, bf16* __restrict__ oh, bf16* __restrict__ ol, long n){
    long i=((long)blockIdx.x*256+threadIdx.x)*4;
    if(i>=n) return;
    float4 v=*reinterpret_cast<const float4*>(in+i);
    unsigned h01,l01,h23,l23; split2(v.x,v.y,h01,l01); split2(v.z,v.w,h23,l23);
    *reinterpret_cast<uint2*>(oh+i)=make_uint2(h01,h23);
    *reinterpret_cast<uint2*>(ol+i)=make_uint2(l01,l23);
}

// ---------------------------------------------------------------------------
// Generic split-bf16 mma.sync GEMM (projections + final): C = A B^T (+bias)(+resid)
// ---------------------------------------------------------------------------
__global__ __launch_bounds__(256) void gemm_mma(
    const bf16* __restrict__ ah,const bf16* __restrict__ al,
    const bf16* __restrict__ bh,const bf16* __restrict__ bl,
    const float* __restrict__ bias,const float* __restrict__ resid,
    float* __restrict__ C,int K,int N)
{
    extern __shared__ char smem[];
    const uint32_t sb=smem_u32(smem);
    const uint32_t sAh=sb, sAl=sb+16384, sBh=sb+32768, sBl=sb+49152;
    const int tid=threadIdx.x, wid=tid>>5, lane=tid&31;
    const int m0=blockIdx.y<<7, n0=blockIdx.x<<7;
    const int wm=(wid&3)<<5, wn=(wid>>2)<<6;
    const bf16* Ah=ah+(long)m0*K; const bf16* Al=al+(long)m0*K;
    const bf16* Bh=bh+(long)n0*K; const bf16* Bl=bl+(long)n0*K;

    float acc[2][8][4]={};
    for(int k0=0;k0<K;k0+=64){
        fill_pair<128>(smem,       smem+16384, Ah+k0, Al+k0, K, tid);
        fill_pair<128>(smem+32768, smem+49152, Bh+k0, Bl+k0, K, tid);
        __syncthreads();
#pragma unroll
        for(int ks=0;ks<4;ks++){
            uint32_t a_h[2][4], a_l[2][4];
            ldm4(a_h[0], sAh, wm,    ks, lane); ldm4(a_h[1], sAh, wm+16, ks, lane);
            ldm4(a_l[0], sAl, wm,    ks, lane); ldm4(a_l[1], sAl, wm+16, ks, lane);
            uint32_t b_h[4][4], b_l[4][4];
#pragma unroll
            for(int j=0;j<4;j++){
                ldm4(b_h[j], sBh, wn+(j<<4), ks, lane);
                ldm4(b_l[j], sBl, wn+(j<<4), ks, lane);
            }
#pragma unroll
            for(int mi=0;mi<2;mi++)
#pragma unroll
                for(int j=0;j<4;j++){
                    mma16816(acc[mi][2*j],   a_h[mi], b_h[j][0], b_h[j][2]);
                    mma16816(acc[mi][2*j+1], a_h[mi], b_h[j][1], b_h[j][3]);
                    mma16816(acc[mi][2*j],   a_h[mi], b_l[j][0], b_l[j][2]);
                    mma16816(acc[mi][2*j+1], a_h[mi], b_l[j][1], b_l[j][3]);
                    mma16816(acc[mi][2*j],   a_l[mi], b_h[j][0], b_h[j][2]);
                    mma16816(acc[mi][2*j+1], a_l[mi], b_h[j][1], b_h[j][3]);
                }
        }
        __syncthreads();
    }
#pragma unroll
    for(int mi=0;mi<2;mi++)
#pragma unroll
        for(int jj=0;jj<8;jj++){
            float* d=acc[mi][jj];
            int col=n0+wn+(jj<<3)+((lane&3)<<1);
            long row=m0+wm+(mi<<4)+(lane>>2);
            float2 v0=make_float2(d[0],d[1]), v1=make_float2(d[2],d[3]);
            if(bias){
                float2 bv=*reinterpret_cast<const float2*>(bias+col);
                v0.x+=bv.x; v0.y+=bv.y; v1.x+=bv.x; v1.y+=bv.y;
            }
            if(resid){
                float2 r0=*reinterpret_cast<const float2*>(resid+row*N+col);
                float2 r1=*reinterpret_cast<const float2*>(resid+(row+8)*N+col);
                v0.x+=r0.x; v0.y+=r0.y; v1.x+=r1.x; v1.y+=r1.y;
            }
            *reinterpret_cast<float2*>(C+row*N+col)=v0;
            *reinterpret_cast<float2*>(C+(row+8)*N+col)=v1;
        }
}

// ---- LN (no bias) -> split bf16, scale folded ----
__global__ __launch_bounds__(256) void ln2bf(const float* __restrict__ in,const float* __restrict__ gamma,float scale,
                                             bf16* __restrict__ oh,bf16* __restrict__ ol){
    const long row=blockIdx.x; const float* p=in+row*DM; const int t=threadIdx.x;
    float v0=p[t],v1=p[t+256],v2=p[t+512];
    float s=v0+v1+v2, sq=v0*v0+v1*v1+v2*v2;
#pragma unroll
    for(int o=16;o;o>>=1){ s+=__shfl_xor_sync(~0u,s,o); sq+=__shfl_xor_sync(~0u,sq,o); }
    __shared__ float ss[8],sqs[8];
    int w=t>>5,ln=t&31;
    if(ln==0){ss[w]=s;sqs[w]=sq;} __syncthreads();
    if(w==0){ s=(ln<8)?ss[ln]:0.f; sq=(ln<8)?sqs[ln]:0.f;
#pragma unroll
        for(int o=4;o;o>>=1){ s+=__shfl_xor_sync(~0u,s,o); sq+=__shfl_xor_sync(~0u,sq,o); }
        if(ln==0){ss[0]=s;sqs[0]=sq;} }
    __syncthreads();
    float mu=ss[0]*(1.f/DM), var=sqs[0]*(1.f/DM)-mu*mu, rstd=rsqrtf(var+1e-5f)*scale;
#pragma unroll
    for(int g=0;g<3;g++){
        int c=t+g*256; float y=((g==0?v0:g==1?v1:v2)-mu)*rstd*gamma[c];
        bf16 h=__float2bfloat16(y); oh[row*DM+c]=h; ol[row*DM+c]=__float2bfloat16(y-__bfloat162float(h));
    }
}

// ---------------------------------------------------------------------------
// Scores + fused column-sum: E[z][q][k] = exp(s-5) split-bf16;
// psum[z][qb][k] = per-CTA column partial sums (deterministic, no atomics).
// ---------------------------------------------------------------------------
__global__ __launch_bounds__(256) void scores_mma(
    const bf16* __restrict__ qh,const bf16* __restrict__ ql,
    const bf16* __restrict__ kh,const bf16* __restrict__ kl,
    bf16* __restrict__ Eh, bf16* __restrict__ El, float* __restrict__ psum)
{
    extern __shared__ char smem[];
    const uint32_t sb=smem_u32(smem);
    const uint32_t sAh=sb, sAl=sb+16384, sBh=sb+32768, sBl=sb+49152;
    const int tid=threadIdx.x, wid=tid>>5, lane=tid&31;
    const int z=blockIdx.z, b=z/NH, h=z-b*NH;
    const int m0=blockIdx.y<<7, n0=blockIdx.x<<7;
    const int wm=(wid&3)<<5, wn=(wid>>2)<<6;
    const bf16* Ah=qh+(long)(b*SEQ+m0)*DM+h*HD;
    const bf16* Al=ql+(long)(b*SEQ+m0)*DM+h*HD;
    const bf16* Bh=kh+(long)(b*SEQ+n0)*DM+h*HD;
    const bf16* Bl=kl+(long)(b*SEQ+n0)*DM+h*HD;

    fill_pair<128>(smem,       smem+16384, Ah, Al, DM, tid);
    fill_pair<128>(smem+32768, smem+49152, Bh, Bl, DM, tid);
    __syncthreads();

    float acc[2][8][4]={};
#pragma unroll
    for(int ks=0;ks<4;ks++){
        uint32_t a_h[2][4], a_l[2][4];
        ldm4(a_h[0], sAh, wm,    ks, lane); ldm4(a_h[1], sAh, wm+16, ks, lane);
        ldm4(a_l[0], sAl, wm,    ks, lane); ldm4(a_l[1], sAl, wm+16, ks, lane);
        uint32_t b_h[4][4], b_l[4][4];
#pragma unroll
        for(int j=0;j<4;j++){
            ldm4(b_h[j], sBh, wn+(j<<4), ks, lane);
            ldm4(b_l[j], sBl, wn+(j<<4), ks, lane);
        }
#pragma unroll
        for(int mi=0;mi<2;mi++)
#pragma unroll
            for(int j=0;j<4;j++){
                mma16816(acc[mi][2*j],   a_h[mi], b_h[j][0], b_h[j][2]);
                mma16816(acc[mi][2*j+1], a_h[mi], b_h[j][1], b_h[j][3]);
                mma16816(acc[mi][2*j],   a_h[mi], b_l[j][0], b_l[j][2]);
                mma16816(acc[mi][2*j+1], a_h[mi], b_l[j][1], b_l[j][3]);
                mma16816(acc[mi][2*j],   a_l[mi], b_h[j][0], b_h[j][2]);
                mma16816(acc[mi][2*j+1], a_l[mi], b_h[j][1], b_h[j][3]);
            }
    }

    const long zoff=(long)z*SEQ*SEQ;
    float cs[8][2]={};
#pragma unroll
    for(int mi=0;mi<2;mi++)
#pragma unroll
        for(int jj=0;jj<8;jj++){
            float* d=acc[mi][jj];
            float e0=__expf(d[0]-5.f), e1=__expf(d[1]-5.f);
            float e2=__expf(d[2]-5.f), e3=__expf(d[3]-5.f);
            cs[jj][0]+=e0+e2; cs[jj][1]+=e1+e3;
            int col=n0+wn+(jj<<3)+((lane&3)<<1);
            long row=m0+wm+(mi<<4)+(lane>>2);
            unsigned hp,lp;
            split2(e0,e1,hp,lp);
            *reinterpret_cast<unsigned*>(Eh+zoff+row*SEQ+col)=hp;
            *reinterpret_cast<unsigned*>(El+zoff+row*SEQ+col)=lp;
            split2(e2,e3,hp,lp);
            *reinterpret_cast<unsigned*>(Eh+zoff+(row+8)*SEQ+col)=hp;
            *reinterpret_cast<unsigned*>(El+zoff+(row+8)*SEQ+col)=lp;
        }
    // reduce column sums: within warp over row-groups, then across the 4 m-warps
    __shared__ float css[4][128];
#pragma unroll
    for(int jj=0;jj<8;jj++)
#pragma unroll
        for(int c=0;c<2;c++){
            float v=cs[jj][c];
            v+=__shfl_xor_sync(~0u,v,4); v+=__shfl_xor_sync(~0u,v,8); v+=__shfl_xor_sync(~0u,v,16);
            cs[jj][c]=v;
        }
    if(lane<4){
#pragma unroll
        for(int jj=0;jj<8;jj++){
            int cl=((wid>>2)<<6)+(jj<<3)+(lane<<1);
            css[wid&3][cl]  =cs[jj][0];
            css[wid&3][cl+1]=cs[jj][1];
        }
    }
    __syncthreads();
    if(tid<128){
        float p=css[0][tid]+css[1][tid]+css[2][tid]+css[3][tid];
        psum[((long)z*16+blockIdx.y)*SEQ + n0 + tid]=p;
    }
}

// ---- rsum[z][k] = 1 / sum_qb psum ----
__global__ __launch_bounds__(256) void rsum_k(const float* __restrict__ psum, float* __restrict__ rsum){
    int i=blockIdx.x*256+threadIdx.x;
    int z=i>>11, k=i&2047;
    float s=0.f;
#pragma unroll
    for(int qb=0;qb<16;qb++) s+=psum[((long)z*16+qb)*SEQ+k];
    rsum[i]=1.f/s;
}

// ---- v [8192][768] -> vt split [z][64][2048], scaled by rsum[z][k] ----
__global__ void vtscale(const float* __restrict__ v, const float* __restrict__ rsum,
                        bf16* __restrict__ vth, bf16* __restrict__ vtl){
    __shared__ float tile[32][33];
    int b=blockIdx.z, c0=blockIdx.y*32, t0=blockIdx.x*32;
    int tx=threadIdx.x, ty=threadIdx.y;
#pragma unroll
    for(int j=0;j<32;j+=8) tile[ty+j][tx]=v[(long)(b*SEQ+t0+ty+j)*DM+c0+tx];
    __syncthreads();
    int z=b*NH+(c0>>6), ch=c0&63;
    float rs=rsum[z*SEQ+t0+tx];
#pragma unroll
    for(int j=0;j<32;j+=8){
        float val=tile[tx][ty+j]*rs;
        bf16 h=__float2bfloat16(val);
        long o=((long)z*HD+ch+ty+j)*SEQ+t0+tx;
        vth[o]=h; vtl[o]=__float2bfloat16(val-__bfloat162float(h));
    }
}

// ---------------------------------------------------------------------------
// PV: plain split-bf16 GEMM. O[b*SEQ+q][h*64+c] = sum_k E[z][q][k]*VT'[z][c][k]
// ---------------------------------------------------------------------------
__global__ __launch_bounds__(256) void pv_mma(
    const bf16* __restrict__ Eh,const bf16* __restrict__ El,
    const bf16* __restrict__ vth,const bf16* __restrict__ vtl,
    bf16* __restrict__ oh, bf16* __restrict__ ol)
{
    extern __shared__ char smem[];
    const uint32_t sb=smem_u32(smem);
    const uint32_t sAh=sb, sAl=sb+16384, sBh=sb+32768, sBl=sb+40960;
    const int tid=threadIdx.x, wid=tid>>5, lane=tid&31;
    const int z=blockIdx.y, b=z/NH, h=z-b*NH;
    const int q0=blockIdx.x<<7;
    const int wm=(wid&3)<<5, wn=(wid>>2)<<5;
    const bf16* Ah=Eh+(long)z*SEQ*SEQ+(long)q0*SEQ;
    const bf16* Al=El+(long)z*SEQ*SEQ+(long)q0*SEQ;
    const bf16* Vh=vth+(long)z*HD*SEQ;
    const bf16* Vl=vtl+(long)z*HD*SEQ;

    float acc[2][4][4]={};
    for(int k0=0;k0<SEQ;k0+=64){
        fill_pair<128>(smem,       smem+16384, Ah+k0, Al+k0, SEQ, tid);
        fill_pair<64>(smem+32768, smem+40960, Vh+k0, Vl+k0, SEQ, tid);
        __syncthreads();
#pragma unroll
        for(int ks=0;ks<4;ks++){
            uint32_t a_h[2][4], a_l[2][4];
            ldm4(a_h[0], sAh, wm,    ks, lane); ldm4(a_h[1], sAh, wm+16, ks, lane);
            ldm4(a_l[0], sAl, wm,    ks, lane); ldm4(a_l[1], sAl, wm+16, ks, lane);
            uint32_t b_h[2][4], b_l[2][4];
#pragma unroll
            for(int j=0;j<2;j++){
                ldm4(b_h[j], sBh, wn+(j<<4), ks, lane);
                ldm4(b_l[j], sBl, wn+(j<<4), ks, lane);
            }
#pragma unroll
            for(int mi=0;mi<2;mi++)
#pragma unroll
                for(int j=0;j<2;j++){
                    mma16816(acc[mi][2*j],   a_h[mi], b_h[j][0], b_h[j][2]);
                    mma16816(acc[mi][2*j+1], a_h[mi], b_h[j][1], b_h[j][3]);
                    mma16816(acc[mi][2*j],   a_h[mi], b_l[j][0], b_l[j][2]);
                    mma16816(acc[mi][2*j+1], a_h[mi], b_l[j][1], b_l[j][3]);
                    mma16816(acc[mi][2*j],   a_l[mi], b_h[j][0], b_h[j][2]);
                    mma16816(acc[mi][2*j+1], a_l[mi], b_h[j][1], b_h[j][3]);
                }
        }
        __syncthreads();
    }
#pragma unroll
    for(int mi=0;mi<2;mi++)
#pragma unroll
        for(int jj=0;jj<4;jj++){
            float* d=acc[mi][jj];
            int col=h*HD+wn+(jj<<3)+((lane&3)<<1);
            long row=(long)b*SEQ+q0+wm+(mi<<4)+(lane>>2);
            unsigned hp,lp;
            split2(d[0],d[1],hp,lp);
            *reinterpret_cast<unsigned*>(oh+row*DM+col)=hp;
            *reinterpret_cast<unsigned*>(ol+row*DM+col)=lp;
            split2(d[2],d[3],hp,lp);
            *reinterpret_cast<unsigned*>(oh+(row+8)*DM+col)=hp;
            *reinterpret_cast<unsigned*>(ol+(row+8)*DM+col)=lp;
        }
}

extern "C" void kernel_launch(void* const* d_in, const int* in_sizes, int n_in,
                              void* d_out, int out_size)
{
    const float* x =(const float*)d_in[0];
    const float* Wq=(const float*)d_in[1];
    const float* Wk=(const float*)d_in[2];
    const float* bk=(const float*)d_in[3];
    const float* Wv=(const float*)d_in[4];
    const float* bv=(const float*)d_in[5];
    const float* gq=(const float*)d_in[6];
    const float* gk=(const float*)d_in[7];
    const float* Wo=(const float*)d_in[8];
    const float* bo=(const float*)d_in[9];
    float* out=(float*)d_out;

    bf16 *xh,*xl,*wh,*wl,*qh,*ql,*kh,*kl,*vth,*vtl,*eh,*el,*oh,*ol;
    float *q,*k,*v,*psum,*rsum;
    cudaGetSymbolAddress((void**)&xh,g_xh); cudaGetSymbolAddress((void**)&xl,g_xl);
    cudaGetSymbolAddress((void**)&wh,g_wh); cudaGetSymbolAddress((void**)&wl,g_wl);
    cudaGetSymbolAddress((void**)&q,g_q); cudaGetSymbolAddress((void**)&k,g_k);
    cudaGetSymbolAddress((void**)&v,g_v);
    cudaGetSymbolAddress((void**)&qh,g_qh); cudaGetSymbolAddress((void**)&ql,g_ql);
    cudaGetSymbolAddress((void**)&kh,g_kh); cudaGetSymbolAddress((void**)&kl,g_kl);
    cudaGetSymbolAddress((void**)&vth,g_vth); cudaGetSymbolAddress((void**)&vtl,g_vtl);
    cudaGetSymbolAddress((void**)&eh,g_eh); cudaGetSymbolAddress((void**)&el,g_el);
    cudaGetSymbolAddress((void**)&psum,g_psum); cudaGetSymbolAddress((void**)&rsum,g_rsum);
    cudaGetSymbolAddress((void**)&oh,g_oh); cudaGetSymbolAddress((void**)&ol,g_ol);

    cudaFuncSetAttribute(gemm_mma,   cudaFuncAttributeMaxDynamicSharedMemorySize, 65536);
    cudaFuncSetAttribute(scores_mma, cudaFuncAttributeMaxDynamicSharedMemorySize, 65536);
    cudaFuncSetAttribute(pv_mma,     cudaFuncAttributeMaxDynamicSharedMemorySize, 49152);

    const long NX=(long)ROWS*DM, NW=(long)DM*DM;
    split_k<<<NX/1024,256>>>(x, xh, xl, NX);
    split_k<<<NW/1024,256>>>(Wq, wh+0*NW, wl+0*NW, NW);
    split_k<<<NW/1024,256>>>(Wk, wh+1*NW, wl+1*NW, NW);
    split_k<<<NW/1024,256>>>(Wv, wh+2*NW, wl+2*NW, NW);
    split_k<<<NW/1024,256>>>(Wo, wh+3*NW, wl+3*NW, NW);

    dim3 gp(DM/128, ROWS/128);
    gemm_mma<<<gp,256,65536>>>(xh,xl, wh+0*NW,wl+0*NW, nullptr, nullptr, q, DM, DM);
    gemm_mma<<<gp,256,65536>>>(xh,xl, wh+1*NW,wl+1*NW, bk,      nullptr, k, DM, DM);
    gemm_mma<<<gp,256,65536>>>(xh,xl, wh+2*NW,wl+2*NW, bv,      nullptr, v, DM, DM);

    ln2bf<<<ROWS,256>>>(q, gq, 0.125f, qh, ql);
    ln2bf<<<ROWS,256>>>(k, gk, 1.0f,   kh, kl);

    scores_mma<<<dim3(SEQ/128, SEQ/128, ZBN),256,65536>>>(qh,ql,kh,kl, eh,el, psum);
    rsum_k<<<ZBN*SEQ/256,256>>>(psum, rsum);
    vtscale<<<dim3(SEQ/32, DM/32, 4), dim3(32,8)>>>(v, rsum, vth, vtl);

    pv_mma<<<dim3(SEQ/128, ZBN),256,49152>>>(eh, el, vth, vtl, oh, ol);

    gemm_mma<<<gp,256,65536>>>(oh,ol, wh+3*NW,wl+3*NW, bo, x, out, DM, DM);
}

// round 8
// speedup vs baseline: 2.9426x; 1.3963x over previous
#include <cuda_runtime.h>
#include <cuda_bf16.h>
#include <cuda_fp16.h>
#include <cstdint>

#define SEQ 2048
#define DM 768
#define NH 12
#define HD 64
#define ROWS 8192
#define ZBN 48
typedef __nv_bfloat16 bf16;
typedef __half f16;

// ---------------- scratch ----------------
__device__ __align__(16) bf16 g_xh[ROWS*DM], g_xl[ROWS*DM];
__device__ __align__(16) bf16 g_wqh[DM*DM], g_wql[DM*DM], g_wkh[DM*DM], g_wkl[DM*DM];
__device__ __align__(16) f16  g_x16[ROWS*DM], g_wv16[DM*DM], g_wo16[DM*DM];
__device__ __align__(16) float g_q[ROWS*DM], g_k[ROWS*DM], g_v[ROWS*DM];
__device__ __align__(16) bf16 g_qh[ROWS*DM], g_ql[ROWS*DM], g_kh[ROWS*DM], g_kl[ROWS*DM];
__device__ __align__(16) f16  g_vt[(long)ZBN*HD*SEQ];
__device__ __align__(16) f16  g_E[(long)ZBN*SEQ*SEQ];
__device__ __align__(16) float g_psum[(long)ZBN*16*SEQ];
__device__ __align__(16) float g_rsum[ZBN*SEQ];
__device__ __align__(16) f16  g_o16[ROWS*DM];

#define SWZ(o) ((o)^(((o)>>3)&0x70))

__device__ __forceinline__ uint32_t smem_u32(const void* p){
    uint32_t a; asm("{ .reg .u64 t; cvta.to.shared.u64 t, %1; cvt.u32.u64 %0, t; }":"=r"(a):"l"(p)); return a;
}
__device__ __forceinline__ void split2(float a,float b,unsigned&hp,unsigned&lp){
    __nv_bfloat162 h=__floats2bfloat162_rn(a,b); float2 hf=__bfloat1622float2(h);
    __nv_bfloat162 l=__floats2bfloat162_rn(a-hf.x,b-hf.y);
    hp=*reinterpret_cast<unsigned*>(&h); lp=*reinterpret_cast<unsigned*>(&l);
}
__device__ __forceinline__ void ldm4(uint32_t* r, uint32_t base, int row0, int ks, int lane){
    uint32_t addr = base + SWZ((unsigned)((row0+(lane&15))<<7) + (unsigned)(((ks<<1)+(lane>>4))<<4));
    asm volatile("ldmatrix.sync.aligned.m8n8.x4.shared.b16 {%0,%1,%2,%3}, [%4];"
        :"=r"(r[0]),"=r"(r[1]),"=r"(r[2]),"=r"(r[3]):"r"(addr));
}
__device__ __forceinline__ void mma_bf(float* d, const uint32_t* a, uint32_t b0, uint32_t b1){
    asm volatile("mma.sync.aligned.m16n8k16.row.col.f32.bf16.bf16.f32 "
        "{%0,%1,%2,%3},{%4,%5,%6,%7},{%8,%9},{%0,%1,%2,%3};"
        : "+f"(d[0]),"+f"(d[1]),"+f"(d[2]),"+f"(d[3])
        : "r"(a[0]),"r"(a[1]),"r"(a[2]),"r"(a[3]),"r"(b0),"r"(b1));
}
__device__ __forceinline__ void mma_hf(float* d, const uint32_t* a, uint32_t b0, uint32_t b1){
    asm volatile("mma.sync.aligned.m16n8k16.row.col.f32.f16.f16.f32 "
        "{%0,%1,%2,%3},{%4,%5,%6,%7},{%8,%9},{%0,%1,%2,%3};"
        : "+f"(d[0]),"+f"(d[1]),"+f"(d[2]),"+f"(d[3])
        : "r"(a[0]),"r"(a[1]),"r"(a[2]),"r"(a[3]),"r"(b0),"r"(b1));
}
template<int ROWSN, typename T>
__device__ __forceinline__ void fill_one(char* s, const T* __restrict__ g, int ldK, int tid){
#pragma unroll
    for(int i=0;i<ROWSN/32;i++){
        int idx=tid+(i<<8); int r=idx>>3, c=idx&7;
        *reinterpret_cast<uint4*>(s+SWZ((unsigned)((r<<7)+(c<<4))))=
            *reinterpret_cast<const uint4*>(g+(long)r*ldK+(c<<3));
    }
}
template<int ROWSN>
__device__ __forceinline__ void fill_pair(char* sh, char* sl,
    const bf16* __restrict__ gh, const bf16* __restrict__ gl, int ldK, int tid){
#pragma unroll
    for(int i=0;i<ROWSN/32;i++){
        int idx=tid+(i<<8); int r=idx>>3, c=idx&7;
        long g=(long)r*ldK + (c<<3);
        unsigned sw=SWZ((unsigned)((r<<7)+(c<<4)));
        *reinterpret_cast<uint4*>(sh+sw)=*reinterpret_cast<const uint4*>(gh+g);
        *reinterpret_cast<uint4*>(sl+sw)=*reinterpret_cast<const uint4*>(gl+g);
    }
}

// ---- fp32 -> split bf16 ----
__global__ __launch_bounds__(256) void split_k(const float* __restrict__ in, bf16* __restrict__ oh, bf16* __restrict__ ol, long n){
    long i=((long)blockIdx.x*256+threadIdx.x)*4;
    if(i>=n) return;
    float4 v=*reinterpret_cast<const float4*>(in+i);
    unsigned h01,l01,h23,l23; split2(v.x,v.y,h01,l01); split2(v.z,v.w,h23,l23);
    *reinterpret_cast<uint2*>(oh+i)=make_uint2(h01,h23);
    *reinterpret_cast<uint2*>(ol+i)=make_uint2(l01,l23);
}
// ---- fp32 -> fp16 ----
__global__ __launch_bounds__(256) void tof16(const float* __restrict__ in, f16* __restrict__ out, long n){
    long i=((long)blockIdx.x*256+threadIdx.x)*4;
    if(i>=n) return;
    float4 v=*reinterpret_cast<const float4*>(in+i);
    __half2 a=__floats2half2_rn(v.x,v.y), b=__floats2half2_rn(v.z,v.w);
    *reinterpret_cast<uint2*>(out+i)=make_uint2(*reinterpret_cast<unsigned*>(&a),*reinterpret_cast<unsigned*>(&b));
}

// ---------------------------------------------------------------------------
// bf16-split 3-pass GEMM (high precision): C = A B^T (+bias)
// ---------------------------------------------------------------------------
__global__ __launch_bounds__(256) void gemm_mma(
    const bf16* __restrict__ ah,const bf16* __restrict__ al,
    const bf16* __restrict__ bh,const bf16* __restrict__ bl,
    const float* __restrict__ bias,
    float* __restrict__ C,int K,int N)
{
    extern __shared__ char smem[];
    const uint32_t sb=smem_u32(smem);
    const uint32_t sAh=sb, sAl=sb+16384, sBh=sb+32768, sBl=sb+49152;
    const int tid=threadIdx.x, wid=tid>>5, lane=tid&31;
    const int m0=blockIdx.y<<7, n0=blockIdx.x<<7;
    const int wm=(wid&3)<<5, wn=(wid>>2)<<6;
    const bf16* Ah=ah+(long)m0*K; const bf16* Al=al+(long)m0*K;
    const bf16* Bh=bh+(long)n0*K; const bf16* Bl=bl+(long)n0*K;

    float acc[2][8][4]={};
    for(int k0=0;k0<K;k0+=64){
        fill_pair<128>(smem,       smem+16384, Ah+k0, Al+k0, K, tid);
        fill_pair<128>(smem+32768, smem+49152, Bh+k0, Bl+k0, K, tid);
        __syncthreads();
#pragma unroll
        for(int ks=0;ks<4;ks++){
            uint32_t a_h[2][4], a_l[2][4];
            ldm4(a_h[0], sAh, wm,    ks, lane); ldm4(a_h[1], sAh, wm+16, ks, lane);
            ldm4(a_l[0], sAl, wm,    ks, lane); ldm4(a_l[1], sAl, wm+16, ks, lane);
            uint32_t b_h[4][4], b_l[4][4];
#pragma unroll
            for(int j=0;j<4;j++){
                ldm4(b_h[j], sBh, wn+(j<<4), ks, lane);
                ldm4(b_l[j], sBl, wn+(j<<4), ks, lane);
            }
#pragma unroll
            for(int mi=0;mi<2;mi++)
#pragma unroll
                for(int j=0;j<4;j++){
                    mma_bf(acc[mi][2*j],   a_h[mi], b_h[j][0], b_h[j][2]);
                    mma_bf(acc[mi][2*j+1], a_h[mi], b_h[j][1], b_h[j][3]);
                    mma_bf(acc[mi][2*j],   a_h[mi], b_l[j][0], b_l[j][2]);
                    mma_bf(acc[mi][2*j+1], a_h[mi], b_l[j][1], b_l[j][3]);
                    mma_bf(acc[mi][2*j],   a_l[mi], b_h[j][0], b_h[j][2]);
                    mma_bf(acc[mi][2*j+1], a_l[mi], b_h[j][1], b_h[j][3]);
                }
        }
        __syncthreads();
    }
#pragma unroll
    for(int mi=0;mi<2;mi++)
#pragma unroll
        for(int jj=0;jj<8;jj++){
            float* d=acc[mi][jj];
            int col=n0+wn+(jj<<3)+((lane&3)<<1);
            long row=m0+wm+(mi<<4)+(lane>>2);
            float2 v0=make_float2(d[0],d[1]), v1=make_float2(d[2],d[3]);
            if(bias){
                float2 bv=*reinterpret_cast<const float2*>(bias+col);
                v0.x+=bv.x; v0.y+=bv.y; v1.x+=bv.x; v1.y+=bv.y;
            }
            *reinterpret_cast<float2*>(C+row*N+col)=v0;
            *reinterpret_cast<float2*>(C+(row+8)*N+col)=v1;
        }
}

// ---------------------------------------------------------------------------
// fp16 single-pass GEMM: C = A B^T (+bias)(+resid)
// ---------------------------------------------------------------------------
__global__ __launch_bounds__(256) void gemm_h(
    const f16* __restrict__ a16,const f16* __restrict__ b16,
    const float* __restrict__ bias,const float* __restrict__ resid,
    float* __restrict__ C,int K,int N)
{
    extern __shared__ char smem[];
    const uint32_t sb=smem_u32(smem);
    const uint32_t sA=sb, sB=sb+16384;
    const int tid=threadIdx.x, wid=tid>>5, lane=tid&31;
    const int m0=blockIdx.y<<7, n0=blockIdx.x<<7;
    const int wm=(wid&3)<<5, wn=(wid>>2)<<6;
    const f16* A=a16+(long)m0*K;
    const f16* B=b16+(long)n0*K;

    float acc[2][8][4]={};
    for(int k0=0;k0<K;k0+=64){
        fill_one<128>(smem,       A+k0, K, tid);
        fill_one<128>(smem+16384, B+k0, K, tid);
        __syncthreads();
#pragma unroll
        for(int ks=0;ks<4;ks++){
            uint32_t av[2][4];
            ldm4(av[0], sA, wm,    ks, lane); ldm4(av[1], sA, wm+16, ks, lane);
            uint32_t bv[4][4];
#pragma unroll
            for(int j=0;j<4;j++) ldm4(bv[j], sB, wn+(j<<4), ks, lane);
#pragma unroll
            for(int mi=0;mi<2;mi++)
#pragma unroll
                for(int j=0;j<4;j++){
                    mma_hf(acc[mi][2*j],   av[mi], bv[j][0], bv[j][2]);
                    mma_hf(acc[mi][2*j+1], av[mi], bv[j][1], bv[j][3]);
                }
        }
        __syncthreads();
    }
#pragma unroll
    for(int mi=0;mi<2;mi++)
#pragma unroll
        for(int jj=0;jj<8;jj++){
            float* d=acc[mi][jj];
            int col=n0+wn+(jj<<3)+((lane&3)<<1);
            long row=m0+wm+(mi<<4)+(lane>>2);
            float2 v0=make_float2(d[0],d[1]), v1=make_float2(d[2],d[3]);
            if(bias){
                float2 bv=*reinterpret_cast<const float2*>(bias+col);
                v0.x+=bv.x; v0.y+=bv.y; v1.x+=bv.x; v1.y+=bv.y;
            }
            if(resid){
                float2 r0=*reinterpret_cast<const float2*>(resid+row*N+col);
                float2 r1=*reinterpret_cast<const float2*>(resid+(row+8)*N+col);
                v0.x+=r0.x; v0.y+=r0.y; v1.x+=r1.x; v1.y+=r1.y;
            }
            *reinterpret_cast<float2*>(C+row*N+col)=v0;
            *reinterpret_cast<float2*>(C+(row+8)*N+col)=v1;
        }
}

// ---- LN (no bias) -> split bf16, scale folded ----
__global__ __launch_bounds__(256) void ln2bf(const float* __restrict__ in,const float* __restrict__ gamma,float scale,
                                             bf16* __restrict__ oh,bf16* __restrict__ ol){
    const long row=blockIdx.x; const float* p=in+row*DM; const int t=threadIdx.x;
    float v0=p[t],v1=p[t+256],v2=p[t+512];
    float s=v0+v1+v2, sq=v0*v0+v1*v1+v2*v2;
#pragma unroll
    for(int o=16;o;o>>=1){ s+=__shfl_xor_sync(~0u,s,o); sq+=__shfl_xor_sync(~0u,sq,o); }
    __shared__ float ss[8],sqs[8];
    int w=t>>5,ln=t&31;
    if(ln==0){ss[w]=s;sqs[w]=sq;} __syncthreads();
    if(w==0){ s=(ln<8)?ss[ln]:0.f; sq=(ln<8)?sqs[ln]:0.f;
#pragma unroll
        for(int o=4;o;o>>=1){ s+=__shfl_xor_sync(~0u,s,o); sq+=__shfl_xor_sync(~0u,sq,o); }
        if(ln==0){ss[0]=s;sqs[0]=sq;} }
    __syncthreads();
    float mu=ss[0]*(1.f/DM), var=sqs[0]*(1.f/DM)-mu*mu, rstd=rsqrtf(var+1e-5f)*scale;
#pragma unroll
    for(int g=0;g<3;g++){
        int c=t+g*256; float y=((g==0?v0:g==1?v1:v2)-mu)*rstd*gamma[c];
        bf16 h=__float2bfloat16(y); oh[row*DM+c]=h; ol[row*DM+c]=__float2bfloat16(y-__bfloat162float(h));
    }
}

// ---------------------------------------------------------------------------
// Scores (3-pass bf16 split) + fused column sums; E = exp(s) stored fp16 (C=0:
// s ~ N(0,1), max ~6.5 over all samples -> E in fp16 normal range).
// ---------------------------------------------------------------------------
__global__ __launch_bounds__(256) void scores_mma(
    const bf16* __restrict__ qh,const bf16* __restrict__ ql,
    const bf16* __restrict__ kh,const bf16* __restrict__ kl,
    f16* __restrict__ E, float* __restrict__ psum)
{
    extern __shared__ char smem[];
    const uint32_t sb=smem_u32(smem);
    const uint32_t sAh=sb, sAl=sb+16384, sBh=sb+32768, sBl=sb+49152;
    const int tid=threadIdx.x, wid=tid>>5, lane=tid&31;
    const int z=blockIdx.z, b=z/NH, h=z-b*NH;
    const int m0=blockIdx.y<<7, n0=blockIdx.x<<7;
    const int wm=(wid&3)<<5, wn=(wid>>2)<<6;
    const bf16* Ah=qh+(long)(b*SEQ+m0)*DM+h*HD;
    const bf16* Al=ql+(long)(b*SEQ+m0)*DM+h*HD;
    const bf16* Bh=kh+(long)(b*SEQ+n0)*DM+h*HD;
    const bf16* Bl=kl+(long)(b*SEQ+n0)*DM+h*HD;

    fill_pair<128>(smem,       smem+16384, Ah, Al, DM, tid);
    fill_pair<128>(smem+32768, smem+49152, Bh, Bl, DM, tid);
    __syncthreads();

    float acc[2][8][4]={};
#pragma unroll
    for(int ks=0;ks<4;ks++){
        uint32_t a_h[2][4], a_l[2][4];
        ldm4(a_h[0], sAh, wm,    ks, lane); ldm4(a_h[1], sAh, wm+16, ks, lane);
        ldm4(a_l[0], sAl, wm,    ks, lane); ldm4(a_l[1], sAl, wm+16, ks, lane);
        uint32_t b_h[4][4], b_l[4][4];
#pragma unroll
        for(int j=0;j<4;j++){
            ldm4(b_h[j], sBh, wn+(j<<4), ks, lane);
            ldm4(b_l[j], sBl, wn+(j<<4), ks, lane);
        }
#pragma unroll
        for(int mi=0;mi<2;mi++)
#pragma unroll
            for(int j=0;j<4;j++){
                mma_bf(acc[mi][2*j],   a_h[mi], b_h[j][0], b_h[j][2]);
                mma_bf(acc[mi][2*j+1], a_h[mi], b_h[j][1], b_h[j][3]);
                mma_bf(acc[mi][2*j],   a_h[mi], b_l[j][0], b_l[j][2]);
                mma_bf(acc[mi][2*j+1], a_h[mi], b_l[j][1], b_l[j][3]);
                mma_bf(acc[mi][2*j],   a_l[mi], b_h[j][0], b_h[j][2]);
                mma_bf(acc[mi][2*j+1], a_l[mi], b_h[j][1], b_h[j][3]);
            }
    }

    const long zoff=(long)z*SEQ*SEQ;
    float cs[8][2]={};
#pragma unroll
    for(int mi=0;mi<2;mi++)
#pragma unroll
        for(int jj=0;jj<8;jj++){
            float* d=acc[mi][jj];
            float e0=__expf(d[0]), e1=__expf(d[1]);
            float e2=__expf(d[2]), e3=__expf(d[3]);
            cs[jj][0]+=e0+e2; cs[jj][1]+=e1+e3;
            int col=n0+wn+(jj<<3)+((lane&3)<<1);
            long row=m0+wm+(mi<<4)+(lane>>2);
            __half2 p0=__floats2half2_rn(e0,e1), p1=__floats2half2_rn(e2,e3);
            *reinterpret_cast<unsigned*>(E+zoff+row*SEQ+col)=*reinterpret_cast<unsigned*>(&p0);
            *reinterpret_cast<unsigned*>(E+zoff+(row+8)*SEQ+col)=*reinterpret_cast<unsigned*>(&p1);
        }
    __shared__ float css[4][128];
#pragma unroll
    for(int jj=0;jj<8;jj++)
#pragma unroll
        for(int c=0;c<2;c++){
            float v=cs[jj][c];
            v+=__shfl_xor_sync(~0u,v,4); v+=__shfl_xor_sync(~0u,v,8); v+=__shfl_xor_sync(~0u,v,16);
            cs[jj][c]=v;
        }
    if(lane<4){
#pragma unroll
        for(int jj=0;jj<8;jj++){
            int cl=((wid>>2)<<6)+(jj<<3)+(lane<<1);
            css[wid&3][cl]  =cs[jj][0];
            css[wid&3][cl+1]=cs[jj][1];
        }
    }
    __syncthreads();
    if(tid<128){
        float p=css[0][tid]+css[1][tid]+css[2][tid]+css[3][tid];
        psum[((long)z*16+blockIdx.y)*SEQ + n0 + tid]=p;
    }
}

// ---- rsum[z][k] = 1 / sum_qb psum ----
__global__ __launch_bounds__(256) void rsum_k(const float* __restrict__ psum, float* __restrict__ rsum){
    int i=blockIdx.x*256+threadIdx.x;
    int z=i>>11, k=i&2047;
    float s=0.f;
#pragma unroll
    for(int qb=0;qb<16;qb++) s+=psum[((long)z*16+qb)*SEQ+k];
    rsum[i]=1.f/s;
}

// ---- v [8192][768] -> vt fp16 [z][64][2048], scaled by rsum[z][k] ----
__global__ void vtscale(const float* __restrict__ v, const float* __restrict__ rsum,
                        f16* __restrict__ vt){
    __shared__ float tile[32][33];
    int b=blockIdx.z, c0=blockIdx.y*32, t0=blockIdx.x*32;
    int tx=threadIdx.x, ty=threadIdx.y;
#pragma unroll
    for(int j=0;j<32;j+=8) tile[ty+j][tx]=v[(long)(b*SEQ+t0+ty+j)*DM+c0+tx];
    __syncthreads();
    int z=b*NH+(c0>>6), ch=c0&63;
    float rs=rsum[z*SEQ+t0+tx];
#pragma unroll
    for(int j=0;j<32;j+=8){
        long o=((long)z*HD+ch+ty+j)*SEQ+t0+tx;
        vt[o]=__float2half_rn(tile[tx][ty+j]*rs);
    }
}

// ---------------------------------------------------------------------------
// PV: fp16 GEMM. O[b*SEQ+q][h*64+c] = sum_k E[z][q][k]*VT[z][c][k]
// ---------------------------------------------------------------------------
__global__ __launch_bounds__(256) void pv_h(
    const f16* __restrict__ E,const f16* __restrict__ vt, f16* __restrict__ o16)
{
    extern __shared__ char smem[];
    const uint32_t sb=smem_u32(smem);
    const uint32_t sA=sb, sB=sb+16384;
    const int tid=threadIdx.x, wid=tid>>5, lane=tid&31;
    const int z=blockIdx.y, b=z/NH, h=z-b*NH;
    const int q0=blockIdx.x<<7;
    const int wm=(wid&3)<<5, wn=(wid>>2)<<5;
    const f16* A=E+(long)z*SEQ*SEQ+(long)q0*SEQ;
    const f16* B=vt+(long)z*HD*SEQ;

    float acc[2][4][4]={};
    for(int k0=0;k0<SEQ;k0+=64){
        fill_one<128>(smem,       A+k0, SEQ, tid);
        fill_one<64>(smem+16384,  B+k0, SEQ, tid);
        __syncthreads();
#pragma unroll
        for(int ks=0;ks<4;ks++){
            uint32_t av[2][4];
            ldm4(av[0], sA, wm,    ks, lane); ldm4(av[1], sA, wm+16, ks, lane);
            uint32_t bv[2][4];
#pragma unroll
            for(int j=0;j<2;j++) ldm4(bv[j], sB, wn+(j<<4), ks, lane);
#pragma unroll
            for(int mi=0;mi<2;mi++)
#pragma unroll
                for(int j=0;j<2;j++){
                    mma_hf(acc[mi][2*j],   av[mi], bv[j][0], bv[j][2]);
                    mma_hf(acc[mi][2*j+1], av[mi], bv[j][1], bv[j][3]);
                }
        }
        __syncthreads();
    }
#pragma unroll
    for(int mi=0;mi<2;mi++)
#pragma unroll
        for(int jj=0;jj<4;jj++){
            float* d=acc[mi][jj];
            int col=h*HD+wn+(jj<<3)+((lane&3)<<1);
            long row=(long)b*SEQ+q0+wm+(mi<<4)+(lane>>2);
            __half2 p0=__floats2half2_rn(d[0],d[1]), p1=__floats2half2_rn(d[2],d[3]);
            *reinterpret_cast<unsigned*>(o16+row*DM+col)=*reinterpret_cast<unsigned*>(&p0);
            *reinterpret_cast<unsigned*>(o16+(row+8)*DM+col)=*reinterpret_cast<unsigned*>(&p1);
        }
}

extern "C" void kernel_launch(void* const* d_in, const int* in_sizes, int n_in,
                              void* d_out, int out_size)
{
    const float* x =(const float*)d_in[0];
    const float* Wq=(const float*)d_in[1];
    const float* Wk=(const float*)d_in[2];
    const float* bk=(const float*)d_in[3];
    const float* Wv=(const float*)d_in[4];
    const float* bv=(const float*)d_in[5];
    const float* gq=(const float*)d_in[6];
    const float* gk=(const float*)d_in[7];
    const float* Wo=(const float*)d_in[8];
    const float* bo=(const float*)d_in[9];
    float* out=(float*)d_out;

    bf16 *xh,*xl,*wqh,*wql,*wkh,*wkl,*qhp,*qlp,*khp,*klp;
    f16 *x16,*wv16,*wo16,*vt,*E,*o16;
    float *q,*k,*v,*psum,*rsum;
    cudaGetSymbolAddress((void**)&xh,g_xh); cudaGetSymbolAddress((void**)&xl,g_xl);
    cudaGetSymbolAddress((void**)&wqh,g_wqh); cudaGetSymbolAddress((void**)&wql,g_wql);
    cudaGetSymbolAddress((void**)&wkh,g_wkh); cudaGetSymbolAddress((void**)&wkl,g_wkl);
    cudaGetSymbolAddress((void**)&x16,g_x16);
    cudaGetSymbolAddress((void**)&wv16,g_wv16); cudaGetSymbolAddress((void**)&wo16,g_wo16);
    cudaGetSymbolAddress((void**)&q,g_q); cudaGetSymbolAddress((void**)&k,g_k);
    cudaGetSymbolAddress((void**)&v,g_v);
    cudaGetSymbolAddress((void**)&qhp,g_qh); cudaGetSymbolAddress((void**)&qlp,g_ql);
    cudaGetSymbolAddress((void**)&khp,g_kh); cudaGetSymbolAddress((void**)&klp,g_kl);
    cudaGetSymbolAddress((void**)&vt,g_vt);
    cudaGetSymbolAddress((void**)&E,g_E);
    cudaGetSymbolAddress((void**)&psum,g_psum); cudaGetSymbolAddress((void**)&rsum,g_rsum);
    cudaGetSymbolAddress((void**)&o16,g_o16);

    cudaFuncSetAttribute(gemm_mma,   cudaFuncAttributeMaxDynamicSharedMemorySize, 65536);
    cudaFuncSetAttribute(gemm_h,     cudaFuncAttributeMaxDynamicSharedMemorySize, 32768);
    cudaFuncSetAttribute(scores_mma, cudaFuncAttributeMaxDynamicSharedMemorySize, 65536);
    cudaFuncSetAttribute(pv_h,       cudaFuncAttributeMaxDynamicSharedMemorySize, 24576);

    const long NX=(long)ROWS*DM, NW=(long)DM*DM;
    split_k<<<NX/1024,256>>>(x, xh, xl, NX);
    split_k<<<NW/1024,256>>>(Wq, wqh, wql, NW);
    split_k<<<NW/1024,256>>>(Wk, wkh, wkl, NW);
    tof16<<<NX/1024,256>>>(x, x16, NX);
    tof16<<<NW/1024,256>>>(Wv, wv16, NW);
    tof16<<<NW/1024,256>>>(Wo, wo16, NW);

    dim3 gp(DM/128, ROWS/128);
    gemm_mma<<<gp,256,65536>>>(xh,xl, wqh,wql, nullptr, q, DM, DM);
    gemm_mma<<<gp,256,65536>>>(xh,xl, wkh,wkl, bk,      k, DM, DM);
    gemm_h  <<<gp,256,32768>>>(x16, wv16, bv, nullptr, v, DM, DM);

    ln2bf<<<ROWS,256>>>(q, gq, 0.125f, qhp, qlp);
    ln2bf<<<ROWS,256>>>(k, gk, 1.0f,   khp, klp);

    scores_mma<<<dim3(SEQ/128, SEQ/128, ZBN),256,65536>>>(qhp,qlp,khp,klp, E, psum);
    rsum_k<<<ZBN*SEQ/256,256>>>(psum, rsum);
    vtscale<<<dim3(SEQ/32, DM/32, 4), dim3(32,8)>>>(v, rsum, vt);

    pv_h<<<dim3(SEQ/128, ZBN),256,24576>>>(E, vt, o16);

    gemm_h<<<gp,256,32768>>>(o16, wo16, bo, x, out, DM, DM);
}

// round 9
// speedup vs baseline: 4.3323x; 1.4723x over previous
#include <cuda_runtime.h>
#include <cuda_bf16.h>
#include <cuda_fp16.h>
#include <cstdint>

#define SEQ 2048
#define DM 768
#define NH 12
#define HD 64
#define ROWS 8192
#define ZBN 48
typedef __nv_bfloat16 bf16;
typedef __half f16;

// ---------------- scratch ----------------
__device__ __align__(16) f16  g_x16[ROWS*DM];
__device__ __align__(16) f16  g_w16[4][DM*DM];
__device__ __align__(16) float g_q[ROWS*DM], g_k[ROWS*DM], g_v[ROWS*DM];
__device__ __align__(16) bf16 g_qh[ROWS*DM], g_ql[ROWS*DM], g_kh[ROWS*DM], g_kl[ROWS*DM];
__device__ __align__(16) f16  g_vt[(long)ZBN*HD*SEQ];
__device__ __align__(16) f16  g_E[(long)ZBN*SEQ*SEQ];
__device__ __align__(16) float g_psum[(long)ZBN*16*SEQ];
__device__ __align__(16) float g_rsum[ZBN*SEQ];
__device__ __align__(16) f16  g_o16[ROWS*DM];

#define SWZ(o) ((o)^(((o)>>3)&0x70))
#define CPCOMMIT() asm volatile("cp.async.commit_group;":::"memory")
#define CPWAIT1()  asm volatile("cp.async.wait_group 1;":::"memory")
#define CPWAIT0()  asm volatile("cp.async.wait_group 0;":::"memory")

__device__ __forceinline__ uint32_t smem_u32(const void* p){
    uint32_t a; asm("{ .reg .u64 t; cvta.to.shared.u64 t, %1; cvt.u32.u64 %0, t; }":"=r"(a):"l"(p)); return a;
}
__device__ __forceinline__ void split2(float a,float b,unsigned&hp,unsigned&lp){
    __nv_bfloat162 h=__floats2bfloat162_rn(a,b); float2 hf=__bfloat1622float2(h);
    __nv_bfloat162 l=__floats2bfloat162_rn(a-hf.x,b-hf.y);
    hp=*reinterpret_cast<unsigned*>(&h); lp=*reinterpret_cast<unsigned*>(&l);
}
__device__ __forceinline__ void ldm4(uint32_t* r, uint32_t base, int row0, int ks, int lane){
    uint32_t addr = base + SWZ((unsigned)((row0+(lane&15))<<7) + (unsigned)(((ks<<1)+(lane>>4))<<4));
    asm volatile("ldmatrix.sync.aligned.m8n8.x4.shared.b16 {%0,%1,%2,%3}, [%4];"
        :"=r"(r[0]),"=r"(r[1]),"=r"(r[2]),"=r"(r[3]):"r"(addr));
}
__device__ __forceinline__ void mma_bf(float* d, const uint32_t* a, uint32_t b0, uint32_t b1){
    asm volatile("mma.sync.aligned.m16n8k16.row.col.f32.bf16.bf16.f32 "
        "{%0,%1,%2,%3},{%4,%5,%6,%7},{%8,%9},{%0,%1,%2,%3};"
        : "+f"(d[0]),"+f"(d[1]),"+f"(d[2]),"+f"(d[3])
        : "r"(a[0]),"r"(a[1]),"r"(a[2]),"r"(a[3]),"r"(b0),"r"(b1));
}
__device__ __forceinline__ void mma_hf(float* d, const uint32_t* a, uint32_t b0, uint32_t b1){
    asm volatile("mma.sync.aligned.m16n8k16.row.col.f32.f16.f16.f32 "
        "{%0,%1,%2,%3},{%4,%5,%6,%7},{%8,%9},{%0,%1,%2,%3};"
        : "+f"(d[0]),"+f"(d[1]),"+f"(d[2]),"+f"(d[3])
        : "r"(a[0]),"r"(a[1]),"r"(a[2]),"r"(a[3]),"r"(b0),"r"(b1));
}
// cp.async fill of ROWSN x 64 (2-byte) tile into SW128 smem
template<int ROWSN, typename T>
__device__ __forceinline__ void cpfill(uint32_t s, const T* __restrict__ g, int ldK, int tid){
#pragma unroll
    for(int i=0;i<ROWSN/32;i++){
        int idx=tid+(i<<8); int r=idx>>3, c=idx&7;
        uint32_t dst=s+SWZ((unsigned)((r<<7)+(c<<4)));
        const void* src=g+(long)r*ldK+(c<<3);
        asm volatile("cp.async.cg.shared.global [%0], [%1], 16;"::"r"(dst),"l"(src):"memory");
    }
}
template<int ROWSN>
__device__ __forceinline__ void fill_pair(char* sh, char* sl,
    const bf16* __restrict__ gh, const bf16* __restrict__ gl, int ldK, int tid){
#pragma unroll
    for(int i=0;i<ROWSN/32;i++){
        int idx=tid+(i<<8); int r=idx>>3, c=idx&7;
        long g=(long)r*ldK + (c<<3);
        unsigned sw=SWZ((unsigned)((r<<7)+(c<<4)));
        *reinterpret_cast<uint4*>(sh+sw)=*reinterpret_cast<const uint4*>(gh+g);
        *reinterpret_cast<uint4*>(sl+sw)=*reinterpret_cast<const uint4*>(gl+g);
    }
}

// ---- fp32 -> fp16 ----
__global__ __launch_bounds__(256) void tof16(const float* __restrict__ in, f16* __restrict__ out, long n){
    long i=((long)blockIdx.x*256+threadIdx.x)*4;
    if(i>=n) return;
    float4 v=*reinterpret_cast<const float4*>(in+i);
    __half2 a=__floats2half2_rn(v.x,v.y), b=__floats2half2_rn(v.z,v.w);
    *reinterpret_cast<uint2*>(out+i)=make_uint2(*reinterpret_cast<unsigned*>(&a),*reinterpret_cast<unsigned*>(&b));
}

// ---------------------------------------------------------------------------
// fp16 single-pass GEMM, cp.async double-buffered: C = A B^T (+bias)(+resid)
// Tile 128x128, BK=64, 8 warps (4m x 2n). Stage stride 32KB, 2 stages.
// ---------------------------------------------------------------------------
__global__ __launch_bounds__(256) void gemm_h(
    const f16* __restrict__ a16,const f16* __restrict__ b16,
    const float* __restrict__ bias,const float* __restrict__ resid,
    float* __restrict__ C,int K,int N)
{
    extern __shared__ char smem[];
    const uint32_t sb=smem_u32(smem);
    const int tid=threadIdx.x, wid=tid>>5, lane=tid&31;
    const int m0=blockIdx.y<<7, n0=blockIdx.x<<7;
    const int wm=(wid&3)<<5, wn=(wid>>2)<<6;
    const f16* A=a16+(long)m0*K;
    const f16* B=b16+(long)n0*K;
    const int NS=K>>6;

    cpfill<128>(sb,       A, K, tid);
    cpfill<128>(sb+16384, B, K, tid);
    CPCOMMIT();

    float acc[2][8][4]={};
    for(int s=0;s<NS;s++){
        if(s+1<NS){
            uint32_t st=sb+((s+1)&1)*32768;
            cpfill<128>(st,       A+(s+1)*64, K, tid);
            cpfill<128>(st+16384, B+(s+1)*64, K, tid);
            CPCOMMIT(); CPWAIT1();
        } else CPWAIT0();
        __syncthreads();
        const uint32_t sA=sb+(s&1)*32768, sB=sA+16384;
#pragma unroll
        for(int ks=0;ks<4;ks++){
            uint32_t av[2][4];
            ldm4(av[0], sA, wm,    ks, lane); ldm4(av[1], sA, wm+16, ks, lane);
            uint32_t bv[4][4];
#pragma unroll
            for(int j=0;j<4;j++) ldm4(bv[j], sB, wn+(j<<4), ks, lane);
#pragma unroll
            for(int mi=0;mi<2;mi++)
#pragma unroll
                for(int j=0;j<4;j++){
                    mma_hf(acc[mi][2*j],   av[mi], bv[j][0], bv[j][2]);
                    mma_hf(acc[mi][2*j+1], av[mi], bv[j][1], bv[j][3]);
                }
        }
        __syncthreads();
    }
#pragma unroll
    for(int mi=0;mi<2;mi++)
#pragma unroll
        for(int jj=0;jj<8;jj++){
            float* d=acc[mi][jj];
            int col=n0+wn+(jj<<3)+((lane&3)<<1);
            long row=m0+wm+(mi<<4)+(lane>>2);
            float2 v0=make_float2(d[0],d[1]), v1=make_float2(d[2],d[3]);
            if(bias){
                float2 bv=*reinterpret_cast<const float2*>(bias+col);
                v0.x+=bv.x; v0.y+=bv.y; v1.x+=bv.x; v1.y+=bv.y;
            }
            if(resid){
                float2 r0=*reinterpret_cast<const float2*>(resid+row*N+col);
                float2 r1=*reinterpret_cast<const float2*>(resid+(row+8)*N+col);
                v0.x+=r0.x; v0.y+=r0.y; v1.x+=r1.x; v1.y+=r1.y;
            }
            *reinterpret_cast<float2*>(C+row*N+col)=v0;
            *reinterpret_cast<float2*>(C+(row+8)*N+col)=v1;
        }
}

// ---- LN (no bias) -> split bf16, scale folded ----
__global__ __launch_bounds__(256) void ln2bf(const float* __restrict__ in,const float* __restrict__ gamma,float scale,
                                             bf16* __restrict__ oh,bf16* __restrict__ ol){
    const long row=blockIdx.x; const float* p=in+row*DM; const int t=threadIdx.x;
    float v0=p[t],v1=p[t+256],v2=p[t+512];
    float s=v0+v1+v2, sq=v0*v0+v1*v1+v2*v2;
#pragma unroll
    for(int o=16;o;o>>=1){ s+=__shfl_xor_sync(~0u,s,o); sq+=__shfl_xor_sync(~0u,sq,o); }
    __shared__ float ss[8],sqs[8];
    int w=t>>5,ln=t&31;
    if(ln==0){ss[w]=s;sqs[w]=sq;} __syncthreads();
    if(w==0){ s=(ln<8)?ss[ln]:0.f; sq=(ln<8)?sqs[ln]:0.f;
#pragma unroll
        for(int o=4;o;o>>=1){ s+=__shfl_xor_sync(~0u,s,o); sq+=__shfl_xor_sync(~0u,sq,o); }
        if(ln==0){ss[0]=s;sqs[0]=sq;} }
    __syncthreads();
    float mu=ss[0]*(1.f/DM), var=sqs[0]*(1.f/DM)-mu*mu, rstd=rsqrtf(var+1e-5f)*scale;
#pragma unroll
    for(int g=0;g<3;g++){
        int c=t+g*256; float y=((g==0?v0:g==1?v1:v2)-mu)*rstd*gamma[c];
        bf16 h=__float2bfloat16(y); oh[row*DM+c]=h; ol[row*DM+c]=__float2bfloat16(y-__bfloat162float(h));
    }
}

// ---------------------------------------------------------------------------
// Scores (3-pass bf16 split) + fused column sums; E = exp(s) fp16, C=0.
// ---------------------------------------------------------------------------
__global__ __launch_bounds__(256) void scores_mma(
    const bf16* __restrict__ qh,const bf16* __restrict__ ql,
    const bf16* __restrict__ kh,const bf16* __restrict__ kl,
    f16* __restrict__ E, float* __restrict__ psum)
{
    extern __shared__ char smem[];
    const uint32_t sb=smem_u32(smem);
    const uint32_t sAh=sb, sAl=sb+16384, sBh=sb+32768, sBl=sb+49152;
    const int tid=threadIdx.x, wid=tid>>5, lane=tid&31;
    const int z=blockIdx.z, b=z/NH, h=z-b*NH;
    const int m0=blockIdx.y<<7, n0=blockIdx.x<<7;
    const int wm=(wid&3)<<5, wn=(wid>>2)<<6;
    const bf16* Ah=qh+(long)(b*SEQ+m0)*DM+h*HD;
    const bf16* Al=ql+(long)(b*SEQ+m0)*DM+h*HD;
    const bf16* Bh=kh+(long)(b*SEQ+n0)*DM+h*HD;
    const bf16* Bl=kl+(long)(b*SEQ+n0)*DM+h*HD;

    fill_pair<128>(smem,       smem+16384, Ah, Al, DM, tid);
    fill_pair<128>(smem+32768, smem+49152, Bh, Bl, DM, tid);
    __syncthreads();

    float acc[2][8][4]={};
#pragma unroll
    for(int ks=0;ks<4;ks++){
        uint32_t a_h[2][4], a_l[2][4];
        ldm4(a_h[0], sAh, wm,    ks, lane); ldm4(a_h[1], sAh, wm+16, ks, lane);
        ldm4(a_l[0], sAl, wm,    ks, lane); ldm4(a_l[1], sAl, wm+16, ks, lane);
        uint32_t b_h[4][4], b_l[4][4];
#pragma unroll
        for(int j=0;j<4;j++){
            ldm4(b_h[j], sBh, wn+(j<<4), ks, lane);
            ldm4(b_l[j], sBl, wn+(j<<4), ks, lane);
        }
#pragma unroll
        for(int mi=0;mi<2;mi++)
#pragma unroll
            for(int j=0;j<4;j++){
                mma_bf(acc[mi][2*j],   a_h[mi], b_h[j][0], b_h[j][2]);
                mma_bf(acc[mi][2*j+1], a_h[mi], b_h[j][1], b_h[j][3]);
                mma_bf(acc[mi][2*j],   a_h[mi], b_l[j][0], b_l[j][2]);
                mma_bf(acc[mi][2*j+1], a_h[mi], b_l[j][1], b_l[j][3]);
                mma_bf(acc[mi][2*j],   a_l[mi], b_h[j][0], b_h[j][2]);
                mma_bf(acc[mi][2*j+1], a_l[mi], b_h[j][1], b_h[j][3]);
            }
    }

    const long zoff=(long)z*SEQ*SEQ;
    float cs[8][2]={};
#pragma unroll
    for(int mi=0;mi<2;mi++)
#pragma unroll
        for(int jj=0;jj<8;jj++){
            float* d=acc[mi][jj];
            float e0=__expf(d[0]), e1=__expf(d[1]);
            float e2=__expf(d[2]), e3=__expf(d[3]);
            cs[jj][0]+=e0+e2; cs[jj][1]+=e1+e3;
            int col=n0+wn+(jj<<3)+((lane&3)<<1);
            long row=m0+wm+(mi<<4)+(lane>>2);
            __half2 p0=__floats2half2_rn(e0,e1), p1=__floats2half2_rn(e2,e3);
            *reinterpret_cast<unsigned*>(E+zoff+row*SEQ+col)=*reinterpret_cast<unsigned*>(&p0);
            *reinterpret_cast<unsigned*>(E+zoff+(row+8)*SEQ+col)=*reinterpret_cast<unsigned*>(&p1);
        }
    __shared__ float css[4][128];
#pragma unroll
    for(int jj=0;jj<8;jj++)
#pragma unroll
        for(int c=0;c<2;c++){
            float v=cs[jj][c];
            v+=__shfl_xor_sync(~0u,v,4); v+=__shfl_xor_sync(~0u,v,8); v+=__shfl_xor_sync(~0u,v,16);
            cs[jj][c]=v;
        }
    if(lane<4){
#pragma unroll
        for(int jj=0;jj<8;jj++){
            int cl=((wid>>2)<<6)+(jj<<3)+(lane<<1);
            css[wid&3][cl]  =cs[jj][0];
            css[wid&3][cl+1]=cs[jj][1];
        }
    }
    __syncthreads();
    if(tid<128){
        float p=css[0][tid]+css[1][tid]+css[2][tid]+css[3][tid];
        psum[((long)z*16+blockIdx.y)*SEQ + n0 + tid]=p;
    }
}

// ---- rsum[z][k] = 1 / sum_qb psum ----
__global__ __launch_bounds__(256) void rsum_k(const float* __restrict__ psum, float* __restrict__ rsum){
    int i=blockIdx.x*256+threadIdx.x;
    int z=i>>11, k=i&2047;
    float s=0.f;
#pragma unroll
    for(int qb=0;qb<16;qb++) s+=psum[((long)z*16+qb)*SEQ+k];
    rsum[i]=1.f/s;
}

// ---- v [8192][768] -> vt fp16 [z][64][2048], scaled by rsum[z][k] ----
__global__ void vtscale(const float* __restrict__ v, const float* __restrict__ rsum,
                        f16* __restrict__ vt){
    __shared__ float tile[32][33];
    int b=blockIdx.z, c0=blockIdx.y*32, t0=blockIdx.x*32;
    int tx=threadIdx.x, ty=threadIdx.y;
#pragma unroll
    for(int j=0;j<32;j+=8) tile[ty+j][tx]=v[(long)(b*SEQ+t0+ty+j)*DM+c0+tx];
    __syncthreads();
    int z=b*NH+(c0>>6), ch=c0&63;
    float rs=rsum[z*SEQ+t0+tx];
#pragma unroll
    for(int j=0;j<32;j+=8){
        long o=((long)z*HD+ch+ty+j)*SEQ+t0+tx;
        vt[o]=__float2half_rn(tile[tx][ty+j]*rs);
    }
}

// ---------------------------------------------------------------------------
// PV: fp16 GEMM, cp.async double-buffered. Stage stride 24KB, 2 stages.
// ---------------------------------------------------------------------------
__global__ __launch_bounds__(256) void pv_h(
    const f16* __restrict__ E,const f16* __restrict__ vt, f16* __restrict__ o16)
{
    extern __shared__ char smem[];
    const uint32_t sb=smem_u32(smem);
    const int tid=threadIdx.x, wid=tid>>5, lane=tid&31;
    const int z=blockIdx.y, b=z/NH, h=z-b*NH;
    const int q0=blockIdx.x<<7;
    const int wm=(wid&3)<<5, wn=(wid>>2)<<5;
    const f16* A=E+(long)z*SEQ*SEQ+(long)q0*SEQ;
    const f16* B=vt+(long)z*HD*SEQ;

    cpfill<128>(sb,       A, SEQ, tid);
    cpfill<64>(sb+16384,  B, SEQ, tid);
    CPCOMMIT();

    float acc[2][4][4]={};
    for(int s=0;s<32;s++){
        if(s+1<32){
            uint32_t st=sb+((s+1)&1)*24576;
            cpfill<128>(st,       A+(s+1)*64, SEQ, tid);
            cpfill<64>(st+16384,  B+(s+1)*64, SEQ, tid);
            CPCOMMIT(); CPWAIT1();
        } else CPWAIT0();
        __syncthreads();
        const uint32_t sA=sb+(s&1)*24576, sB=sA+16384;
#pragma unroll
        for(int ks=0;ks<4;ks++){
            uint32_t av[2][4];
            ldm4(av[0], sA, wm,    ks, lane); ldm4(av[1], sA, wm+16, ks, lane);
            uint32_t bv[2][4];
#pragma unroll
            for(int j=0;j<2;j++) ldm4(bv[j], sB, wn+(j<<4), ks, lane);
#pragma unroll
            for(int mi=0;mi<2;mi++)
#pragma unroll
                for(int j=0;j<2;j++){
                    mma_hf(acc[mi][2*j],   av[mi], bv[j][0], bv[j][2]);
                    mma_hf(acc[mi][2*j+1], av[mi], bv[j][1], bv[j][3]);
                }
        }
        __syncthreads();
    }
#pragma unroll
    for(int mi=0;mi<2;mi++)
#pragma unroll
        for(int jj=0;jj<4;jj++){
            float* d=acc[mi][jj];
            int col=h*HD+wn+(jj<<3)+((lane&3)<<1);
            long row=(long)b*SEQ+q0+wm+(mi<<4)+(lane>>2);
            __half2 p0=__floats2half2_rn(d[0],d[1]), p1=__floats2half2_rn(d[2],d[3]);
            *reinterpret_cast<unsigned*>(o16+row*DM+col)=*reinterpret_cast<unsigned*>(&p0);
            *reinterpret_cast<unsigned*>(o16+(row+8)*DM+col)=*reinterpret_cast<unsigned*>(&p1);
        }
}

extern "C" void kernel_launch(void* const* d_in, const int* in_sizes, int n_in,
                              void* d_out, int out_size)
{
    const float* x =(const float*)d_in[0];
    const float* Wq=(const float*)d_in[1];
    const float* Wk=(const float*)d_in[2];
    const float* bk=(const float*)d_in[3];
    const float* Wv=(const float*)d_in[4];
    const float* bv=(const float*)d_in[5];
    const float* gq=(const float*)d_in[6];
    const float* gk=(const float*)d_in[7];
    const float* Wo=(const float*)d_in[8];
    const float* bo=(const float*)d_in[9];
    float* out=(float*)d_out;

    f16 *x16,*w16,*vt,*E,*o16;
    bf16 *qh,*ql,*kh,*kl;
    float *q,*k,*v,*psum,*rsum;
    cudaGetSymbolAddress((void**)&x16,g_x16); cudaGetSymbolAddress((void**)&w16,g_w16);
    cudaGetSymbolAddress((void**)&q,g_q); cudaGetSymbolAddress((void**)&k,g_k);
    cudaGetSymbolAddress((void**)&v,g_v);
    cudaGetSymbolAddress((void**)&qh,g_qh); cudaGetSymbolAddress((void**)&ql,g_ql);
    cudaGetSymbolAddress((void**)&kh,g_kh); cudaGetSymbolAddress((void**)&kl,g_kl);
    cudaGetSymbolAddress((void**)&vt,g_vt);
    cudaGetSymbolAddress((void**)&E,g_E);
    cudaGetSymbolAddress((void**)&psum,g_psum); cudaGetSymbolAddress((void**)&rsum,g_rsum);
    cudaGetSymbolAddress((void**)&o16,g_o16);

    cudaFuncSetAttribute(gemm_h,     cudaFuncAttributeMaxDynamicSharedMemorySize, 65536);
    cudaFuncSetAttribute(scores_mma, cudaFuncAttributeMaxDynamicSharedMemorySize, 65536);
    cudaFuncSetAttribute(pv_h,       cudaFuncAttributeMaxDynamicSharedMemorySize, 49152);

    const long NX=(long)ROWS*DM, NW=(long)DM*DM;
    tof16<<<NX/1024,256>>>(x, x16, NX);
    tof16<<<NW/1024,256>>>(Wq, w16+0*NW, NW);
    tof16<<<NW/1024,256>>>(Wk, w16+1*NW, NW);
    tof16<<<NW/1024,256>>>(Wv, w16+2*NW, NW);
    tof16<<<NW/1024,256>>>(Wo, w16+3*NW, NW);

    dim3 gp(DM/128, ROWS/128);
    gemm_h<<<gp,256,65536>>>(x16, w16+0*NW, nullptr, nullptr, q, DM, DM);
    gemm_h<<<gp,256,65536>>>(x16, w16+1*NW, bk,      nullptr, k, DM, DM);
    gemm_h<<<gp,256,65536>>>(x16, w16+2*NW, bv,      nullptr, v, DM, DM);

    ln2bf<<<ROWS,256>>>(q, gq, 0.125f, qh, ql);
    ln2bf<<<ROWS,256>>>(k, gk, 1.0f,   kh, kl);

    scores_mma<<<dim3(SEQ/128, SEQ/128, ZBN),256,65536>>>(qh,ql,kh,kl, E, psum);
    rsum_k<<<ZBN*SEQ/256,256>>>(psum, rsum);
    vtscale<<<dim3(SEQ/32, DM/32, 4), dim3(32,8)>>>(v, rsum, vt);

    pv_h<<<dim3(SEQ/128, ZBN),256,24576*2>>>(E, vt, o16);

    gemm_h<<<gp,256,65536>>>(o16, w16+3*NW, bo, x, out, DM, DM);
}

// round 10
// speedup vs baseline: 5.0668x; 1.1696x over previous
#include <cuda_runtime.h>
#include <cuda_fp16.h>
#include <cstdint>

#define SEQ 2048
#define DM 768
#define NH 12
#define HD 64
#define ROWS 8192
#define ZBN 48
typedef __half f16;

// ---------------- scratch ----------------
__device__ __align__(16) f16  g_x16[ROWS*DM];
__device__ __align__(16) f16  g_w16[4][DM*DM];
__device__ __align__(16) float g_q[ROWS*DM], g_k[ROWS*DM], g_v[ROWS*DM];
__device__ __align__(16) f16  g_q16[ROWS*DM], g_k16[ROWS*DM];
__device__ __align__(16) f16  g_vt[(long)ZBN*HD*SEQ];
__device__ __align__(16) f16  g_E[(long)ZBN*SEQ*SEQ];
__device__ __align__(16) float g_psum[(long)ZBN*16*SEQ];
__device__ __align__(16) float g_rsum[ZBN*SEQ];
__device__ __align__(16) f16  g_o16[ROWS*DM];

#define SWZ(o) ((o)^(((o)>>3)&0x70))
#define CPCOMMIT() asm volatile("cp.async.commit_group;":::"memory")
#define CPWAIT1()  asm volatile("cp.async.wait_group 1;":::"memory")
#define CPWAIT0()  asm volatile("cp.async.wait_group 0;":::"memory")

__device__ __forceinline__ uint32_t smem_u32(const void* p){
    uint32_t a; asm("{ .reg .u64 t; cvta.to.shared.u64 t, %1; cvt.u32.u64 %0, t; }":"=r"(a):"l"(p)); return a;
}
__device__ __forceinline__ void ldm4(uint32_t* r, uint32_t base, int row0, int ks, int lane){
    uint32_t addr = base + SWZ((unsigned)((row0+(lane&15))<<7) + (unsigned)(((ks<<1)+(lane>>4))<<4));
    asm volatile("ldmatrix.sync.aligned.m8n8.x4.shared.b16 {%0,%1,%2,%3}, [%4];"
        :"=r"(r[0]),"=r"(r[1]),"=r"(r[2]),"=r"(r[3]):"r"(addr));
}
__device__ __forceinline__ void mma_hf(float* d, const uint32_t* a, uint32_t b0, uint32_t b1){
    asm volatile("mma.sync.aligned.m16n8k16.row.col.f32.f16.f16.f32 "
        "{%0,%1,%2,%3},{%4,%5,%6,%7},{%8,%9},{%0,%1,%2,%3};"
        : "+f"(d[0]),"+f"(d[1]),"+f"(d[2]),"+f"(d[3])
        : "r"(a[0]),"r"(a[1]),"r"(a[2]),"r"(a[3]),"r"(b0),"r"(b1));
}
// cp.async fill of ROWSN x 64 (2-byte) tile into SW128 smem
template<int ROWSN, typename T>
__device__ __forceinline__ void cpfill(uint32_t s, const T* __restrict__ g, int ldK, int tid){
#pragma unroll
    for(int i=0;i<ROWSN/32;i++){
        int idx=tid+(i<<8); int r=idx>>3, c=idx&7;
        uint32_t dst=s+SWZ((unsigned)((r<<7)+(c<<4)));
        const void* src=g+(long)r*ldK+(c<<3);
        asm volatile("cp.async.cg.shared.global [%0], [%1], 16;"::"r"(dst),"l"(src):"memory");
    }
}

// ---- fp32 -> fp16 ----
__global__ __launch_bounds__(256) void tof16(const float* __restrict__ in, f16* __restrict__ out, long n){
    long i=((long)blockIdx.x*256+threadIdx.x)*4;
    if(i>=n) return;
    float4 v=*reinterpret_cast<const float4*>(in+i);
    __half2 a=__floats2half2_rn(v.x,v.y), b=__floats2half2_rn(v.z,v.w);
    *reinterpret_cast<uint2*>(out+i)=make_uint2(*reinterpret_cast<unsigned*>(&a),*reinterpret_cast<unsigned*>(&b));
}

// ---------------------------------------------------------------------------
// fp16 single-pass GEMM, cp.async double-buffered: C = A B^T (+bias)(+resid)
// Tile 128x128, BK=64, 8 warps (4m x 2n). Stage stride 32KB, 2 stages.
// ---------------------------------------------------------------------------
__global__ __launch_bounds__(256) void gemm_h(
    const f16* __restrict__ a16,const f16* __restrict__ b16,
    const float* __restrict__ bias,const float* __restrict__ resid,
    float* __restrict__ C,int K,int N)
{
    extern __shared__ char smem[];
    const uint32_t sb=smem_u32(smem);
    const int tid=threadIdx.x, wid=tid>>5, lane=tid&31;
    const int m0=blockIdx.y<<7, n0=blockIdx.x<<7;
    const int wm=(wid&3)<<5, wn=(wid>>2)<<6;
    const f16* A=a16+(long)m0*K;
    const f16* B=b16+(long)n0*K;
    const int NS=K>>6;

    cpfill<128>(sb,       A, K, tid);
    cpfill<128>(sb+16384, B, K, tid);
    CPCOMMIT();

    float acc[2][8][4]={};
    for(int s=0;s<NS;s++){
        if(s+1<NS){
            uint32_t st=sb+((s+1)&1)*32768;
            cpfill<128>(st,       A+(s+1)*64, K, tid);
            cpfill<128>(st+16384, B+(s+1)*64, K, tid);
            CPCOMMIT(); CPWAIT1();
        } else CPWAIT0();
        __syncthreads();
        const uint32_t sA=sb+(s&1)*32768, sB=sA+16384;
#pragma unroll
        for(int ks=0;ks<4;ks++){
            uint32_t av[2][4];
            ldm4(av[0], sA, wm,    ks, lane); ldm4(av[1], sA, wm+16, ks, lane);
            uint32_t bv[4][4];
#pragma unroll
            for(int j=0;j<4;j++) ldm4(bv[j], sB, wn+(j<<4), ks, lane);
#pragma unroll
            for(int mi=0;mi<2;mi++)
#pragma unroll
                for(int j=0;j<4;j++){
                    mma_hf(acc[mi][2*j],   av[mi], bv[j][0], bv[j][2]);
                    mma_hf(acc[mi][2*j+1], av[mi], bv[j][1], bv[j][3]);
                }
        }
        __syncthreads();
    }
#pragma unroll
    for(int mi=0;mi<2;mi++)
#pragma unroll
        for(int jj=0;jj<8;jj++){
            float* d=acc[mi][jj];
            int col=n0+wn+(jj<<3)+((lane&3)<<1);
            long row=m0+wm+(mi<<4)+(lane>>2);
            float2 v0=make_float2(d[0],d[1]), v1=make_float2(d[2],d[3]);
            if(bias){
                float2 bv=*reinterpret_cast<const float2*>(bias+col);
                v0.x+=bv.x; v0.y+=bv.y; v1.x+=bv.x; v1.y+=bv.y;
            }
            if(resid){
                float2 r0=*reinterpret_cast<const float2*>(resid+row*N+col);
                float2 r1=*reinterpret_cast<const float2*>(resid+(row+8)*N+col);
                v0.x+=r0.x; v0.y+=r0.y; v1.x+=r1.x; v1.y+=r1.y;
            }
            *reinterpret_cast<float2*>(C+row*N+col)=v0;
            *reinterpret_cast<float2*>(C+(row+8)*N+col)=v1;
        }
}

// ---- LN (no bias) -> fp16, scale folded ----
__global__ __launch_bounds__(256) void ln2f16(const float* __restrict__ in,const float* __restrict__ gamma,float scale,
                                              f16* __restrict__ o16){
    const long row=blockIdx.x; const float* p=in+row*DM; const int t=threadIdx.x;
    float v0=p[t],v1=p[t+256],v2=p[t+512];
    float s=v0+v1+v2, sq=v0*v0+v1*v1+v2*v2;
#pragma unroll
    for(int o=16;o;o>>=1){ s+=__shfl_xor_sync(~0u,s,o); sq+=__shfl_xor_sync(~0u,sq,o); }
    __shared__ float ss[8],sqs[8];
    int w=t>>5,ln=t&31;
    if(ln==0){ss[w]=s;sqs[w]=sq;} __syncthreads();
    if(w==0){ s=(ln<8)?ss[ln]:0.f; sq=(ln<8)?sqs[ln]:0.f;
#pragma unroll
        for(int o=4;o;o>>=1){ s+=__shfl_xor_sync(~0u,s,o); sq+=__shfl_xor_sync(~0u,sq,o); }
        if(ln==0){ss[0]=s;sqs[0]=sq;} }
    __syncthreads();
    float mu=ss[0]*(1.f/DM), var=sqs[0]*(1.f/DM)-mu*mu, rstd=rsqrtf(var+1e-5f)*scale;
#pragma unroll
    for(int g=0;g<3;g++){
        int c=t+g*256; float y=((g==0?v0:g==1?v1:v2)-mu)*rstd*gamma[c];
        o16[row*DM+c]=__float2half_rn(y);
    }
}

// ---------------------------------------------------------------------------
// Scores (single-pass fp16) + fused column sums; E = exp(s) fp16 (C=0).
// One k-slab (K=64). Tile 128x128, 8 warps.
// ---------------------------------------------------------------------------
__global__ __launch_bounds__(256) void scores_h(
    const f16* __restrict__ q16,const f16* __restrict__ k16,
    f16* __restrict__ E, float* __restrict__ psum)
{
    extern __shared__ char smem[];
    const uint32_t sb=smem_u32(smem);
    const uint32_t sA=sb, sB=sb+16384;
    const int tid=threadIdx.x, wid=tid>>5, lane=tid&31;
    const int z=blockIdx.z, b=z/NH, h=z-b*NH;
    const int m0=blockIdx.y<<7, n0=blockIdx.x<<7;
    const int wm=(wid&3)<<5, wn=(wid>>2)<<6;
    const f16* A=q16+(long)(b*SEQ+m0)*DM+h*HD;
    const f16* B=k16+(long)(b*SEQ+n0)*DM+h*HD;

    cpfill<128>(sA, A, DM, tid);
    cpfill<128>(sB, B, DM, tid);
    CPCOMMIT(); CPWAIT0();
    __syncthreads();

    float acc[2][8][4]={};
#pragma unroll
    for(int ks=0;ks<4;ks++){
        uint32_t av[2][4];
        ldm4(av[0], sA, wm,    ks, lane); ldm4(av[1], sA, wm+16, ks, lane);
        uint32_t bv[4][4];
#pragma unroll
        for(int j=0;j<4;j++) ldm4(bv[j], sB, wn+(j<<4), ks, lane);
#pragma unroll
        for(int mi=0;mi<2;mi++)
#pragma unroll
            for(int j=0;j<4;j++){
                mma_hf(acc[mi][2*j],   av[mi], bv[j][0], bv[j][2]);
                mma_hf(acc[mi][2*j+1], av[mi], bv[j][1], bv[j][3]);
            }
    }

    const long zoff=(long)z*SEQ*SEQ;
    float cs[8][2]={};
#pragma unroll
    for(int mi=0;mi<2;mi++)
#pragma unroll
        for(int jj=0;jj<8;jj++){
            float* d=acc[mi][jj];
            float e0=__expf(d[0]), e1=__expf(d[1]);
            float e2=__expf(d[2]), e3=__expf(d[3]);
            cs[jj][0]+=e0+e2; cs[jj][1]+=e1+e3;
            int col=n0+wn+(jj<<3)+((lane&3)<<1);
            long row=m0+wm+(mi<<4)+(lane>>2);
            __half2 p0=__floats2half2_rn(e0,e1), p1=__floats2half2_rn(e2,e3);
            *reinterpret_cast<unsigned*>(E+zoff+row*SEQ+col)=*reinterpret_cast<unsigned*>(&p0);
            *reinterpret_cast<unsigned*>(E+zoff+(row+8)*SEQ+col)=*reinterpret_cast<unsigned*>(&p1);
        }
    __shared__ float css[4][128];
#pragma unroll
    for(int jj=0;jj<8;jj++)
#pragma unroll
        for(int c=0;c<2;c++){
            float v=cs[jj][c];
            v+=__shfl_xor_sync(~0u,v,4); v+=__shfl_xor_sync(~0u,v,8); v+=__shfl_xor_sync(~0u,v,16);
            cs[jj][c]=v;
        }
    if(lane<4){
#pragma unroll
        for(int jj=0;jj<8;jj++){
            int cl=((wid>>2)<<6)+(jj<<3)+(lane<<1);
            css[wid&3][cl]  =cs[jj][0];
            css[wid&3][cl+1]=cs[jj][1];
        }
    }
    __syncthreads();
    if(tid<128){
        float p=css[0][tid]+css[1][tid]+css[2][tid]+css[3][tid];
        psum[((long)z*16+blockIdx.y)*SEQ + n0 + tid]=p;
    }
}

// ---- rsum[z][k] = 1 / sum_qb psum ----
__global__ __launch_bounds__(256) void rsum_k(const float* __restrict__ psum, float* __restrict__ rsum){
    int i=blockIdx.x*256+threadIdx.x;
    int z=i>>11, k=i&2047;
    float s=0.f;
#pragma unroll
    for(int qb=0;qb<16;qb++) s+=psum[((long)z*16+qb)*SEQ+k];
    rsum[i]=1.f/s;
}

// ---- v [8192][768] -> vt fp16 [z][64][2048], scaled by rsum[z][k] ----
__global__ void vtscale(const float* __restrict__ v, const float* __restrict__ rsum,
                        f16* __restrict__ vt){
    __shared__ float tile[32][33];
    int b=blockIdx.z, c0=blockIdx.y*32, t0=blockIdx.x*32;
    int tx=threadIdx.x, ty=threadIdx.y;
#pragma unroll
    for(int j=0;j<32;j+=8) tile[ty+j][tx]=v[(long)(b*SEQ+t0+ty+j)*DM+c0+tx];
    __syncthreads();
    int z=b*NH+(c0>>6), ch=c0&63;
    float rs=rsum[z*SEQ+t0+tx];
#pragma unroll
    for(int j=0;j<32;j+=8){
        long o=((long)z*HD+ch+ty+j)*SEQ+t0+tx;
        vt[o]=__float2half_rn(tile[tx][ty+j]*rs);
    }
}

// ---------------------------------------------------------------------------
// PV: fp16 GEMM, cp.async double-buffered. Stage stride 24KB, 2 stages.
// ---------------------------------------------------------------------------
__global__ __launch_bounds__(256) void pv_h(
    const f16* __restrict__ E,const f16* __restrict__ vt, f16* __restrict__ o16)
{
    extern __shared__ char smem[];
    const uint32_t sb=smem_u32(smem);
    const int tid=threadIdx.x, wid=tid>>5, lane=tid&31;
    const int z=blockIdx.y, b=z/NH, h=z-b*NH;
    const int q0=blockIdx.x<<7;
    const int wm=(wid&3)<<5, wn=(wid>>2)<<5;
    const f16* A=E+(long)z*SEQ*SEQ+(long)q0*SEQ;
    const f16* B=vt+(long)z*HD*SEQ;

    cpfill<128>(sb,       A, SEQ, tid);
    cpfill<64>(sb+16384,  B, SEQ, tid);
    CPCOMMIT();

    float acc[2][4][4]={};
    for(int s=0;s<32;s++){
        if(s+1<32){
            uint32_t st=sb+((s+1)&1)*24576;
            cpfill<128>(st,       A+(s+1)*64, SEQ, tid);
            cpfill<64>(st+16384,  B+(s+1)*64, SEQ, tid);
            CPCOMMIT(); CPWAIT1();
        } else CPWAIT0();
        __syncthreads();
        const uint32_t sA=sb+(s&1)*24576, sB=sA+16384;
#pragma unroll
        for(int ks=0;ks<4;ks++){
            uint32_t av[2][4];
            ldm4(av[0], sA, wm,    ks, lane); ldm4(av[1], sA, wm+16, ks, lane);
            uint32_t bv[2][4];
#pragma unroll
            for(int j=0;j<2;j++) ldm4(bv[j], sB, wn+(j<<4), ks, lane);
#pragma unroll
            for(int mi=0;mi<2;mi++)
#pragma unroll
                for(int j=0;j<2;j++){
                    mma_hf(acc[mi][2*j],   av[mi], bv[j][0], bv[j][2]);
                    mma_hf(acc[mi][2*j+1], av[mi], bv[j][1], bv[j][3]);
                }
        }
        __syncthreads();
    }
#pragma unroll
    for(int mi=0;mi<2;mi++)
#pragma unroll
        for(int jj=0;jj<4;jj++){
            float* d=acc[mi][jj];
            int col=h*HD+wn+(jj<<3)+((lane&3)<<1);
            long row=(long)b*SEQ+q0+wm+(mi<<4)+(lane>>2);
            __half2 p0=__floats2half2_rn(d[0],d[1]), p1=__floats2half2_rn(d[2],d[3]);
            *reinterpret_cast<unsigned*>(o16+row*DM+col)=*reinterpret_cast<unsigned*>(&p0);
            *reinterpret_cast<unsigned*>(o16+(row+8)*DM+col)=*reinterpret_cast<unsigned*>(&p1);
        }
}

extern "C" void kernel_launch(void* const* d_in, const int* in_sizes, int n_in,
                              void* d_out, int out_size)
{
    const float* x =(const float*)d_in[0];
    const float* Wq=(const float*)d_in[1];
    const float* Wk=(const float*)d_in[2];
    const float* bk=(const float*)d_in[3];
    const float* Wv=(const float*)d_in[4];
    const float* bv=(const float*)d_in[5];
    const float* gq=(const float*)d_in[6];
    const float* gk=(const float*)d_in[7];
    const float* Wo=(const float*)d_in[8];
    const float* bo=(const float*)d_in[9];
    float* out=(float*)d_out;

    f16 *x16,*w16,*q16,*k16,*vt,*E,*o16;
    float *q,*k,*v,*psum,*rsum;
    cudaGetSymbolAddress((void**)&x16,g_x16); cudaGetSymbolAddress((void**)&w16,g_w16);
    cudaGetSymbolAddress((void**)&q,g_q); cudaGetSymbolAddress((void**)&k,g_k);
    cudaGetSymbolAddress((void**)&v,g_v);
    cudaGetSymbolAddress((void**)&q16,g_q16); cudaGetSymbolAddress((void**)&k16,g_k16);
    cudaGetSymbolAddress((void**)&vt,g_vt);
    cudaGetSymbolAddress((void**)&E,g_E);
    cudaGetSymbolAddress((void**)&psum,g_psum); cudaGetSymbolAddress((void**)&rsum,g_rsum);
    cudaGetSymbolAddress((void**)&o16,g_o16);

    cudaFuncSetAttribute(gemm_h,   cudaFuncAttributeMaxDynamicSharedMemorySize, 65536);
    cudaFuncSetAttribute(scores_h, cudaFuncAttributeMaxDynamicSharedMemorySize, 32768);
    cudaFuncSetAttribute(pv_h,     cudaFuncAttributeMaxDynamicSharedMemorySize, 49152);

    const long NX=(long)ROWS*DM, NW=(long)DM*DM;
    tof16<<<NX/1024,256>>>(x, x16, NX);
    tof16<<<NW/1024,256>>>(Wq, w16+0*NW, NW);
    tof16<<<NW/1024,256>>>(Wk, w16+1*NW, NW);
    tof16<<<NW/1024,256>>>(Wv, w16+2*NW, NW);
    tof16<<<NW/1024,256>>>(Wo, w16+3*NW, NW);

    dim3 gp(DM/128, ROWS/128);
    gemm_h<<<gp,256,65536>>>(x16, w16+0*NW, nullptr, nullptr, q, DM, DM);
    gemm_h<<<gp,256,65536>>>(x16, w16+1*NW, bk,      nullptr, k, DM, DM);
    gemm_h<<<gp,256,65536>>>(x16, w16+2*NW, bv,      nullptr, v, DM, DM);

    ln2f16<<<ROWS,256>>>(q, gq, 0.125f, q16);
    ln2f16<<<ROWS,256>>>(k, gk, 1.0f,   k16);

    scores_h<<<dim3(SEQ/128, SEQ/128, ZBN),256,32768>>>(q16, k16, E, psum);
    rsum_k<<<ZBN*SEQ/256,256>>>(psum, rsum);
    vtscale<<<dim3(SEQ/32, DM/32, 4), dim3(32,8)>>>(v, rsum, vt);

    pv_h<<<dim3(SEQ/128, ZBN),256,24576*2>>>(E, vt, o16);

    gemm_h<<<gp,256,65536>>>(o16, w16+3*NW, bo, x, out, DM, DM);
}

// round 11
// speedup vs baseline: 5.0714x; 1.0009x over previous
#include <cuda_runtime.h>
#include <cuda_fp16.h>
#include <cstdint>

#define SEQ 2048
#define DM 768
#define NH 12
#define HD 64
#define ROWS 8192
#define ZBN 48
typedef __half f16;

// ---------------- scratch ----------------
__device__ __align__(16) f16  g_x16[ROWS*DM];
__device__ __align__(16) f16  g_w16[4][DM*DM];
__device__ __align__(16) float g_q[ROWS*DM], g_k[ROWS*DM], g_v[ROWS*DM];
__device__ __align__(16) f16  g_q16[ROWS*DM], g_k16[ROWS*DM];
__device__ __align__(16) f16  g_vt[(long)ZBN*HD*SEQ];
__device__ __align__(16) f16  g_E[(long)ZBN*SEQ*SEQ];
__device__ __align__(16) float g_psum[(long)ZBN*16*SEQ];
__device__ __align__(16) float g_rsum[ZBN*SEQ];
__device__ __align__(16) f16  g_o16[ROWS*DM];

#define SWZ(o) ((o)^(((o)>>3)&0x70))
#define CPCOMMIT() asm volatile("cp.async.commit_group;":::"memory")
#define CPWAIT1()  asm volatile("cp.async.wait_group 1;":::"memory")
#define CPWAIT0()  asm volatile("cp.async.wait_group 0;":::"memory")

__device__ __forceinline__ uint32_t smem_u32(const void* p){
    uint32_t a; asm("{ .reg .u64 t; cvta.to.shared.u64 t, %1; cvt.u32.u64 %0, t; }":"=r"(a):"l"(p)); return a;
}
__device__ __forceinline__ void ldm4(uint32_t* r, uint32_t base, int row0, int ks, int lane){
    uint32_t addr = base + SWZ((unsigned)((row0+(lane&15))<<7) + (unsigned)(((ks<<1)+(lane>>4))<<4));
    asm volatile("ldmatrix.sync.aligned.m8n8.x4.shared.b16 {%0,%1,%2,%3}, [%4];"
        :"=r"(r[0]),"=r"(r[1]),"=r"(r[2]),"=r"(r[3]):"r"(addr));
}
__device__ __forceinline__ void mma_hf(float* d, const uint32_t* a, uint32_t b0, uint32_t b1){
    asm volatile("mma.sync.aligned.m16n8k16.row.col.f32.f16.f16.f32 "
        "{%0,%1,%2,%3},{%4,%5,%6,%7},{%8,%9},{%0,%1,%2,%3};"
        : "+f"(d[0]),"+f"(d[1]),"+f"(d[2]),"+f"(d[3])
        : "r"(a[0]),"r"(a[1]),"r"(a[2]),"r"(a[3]),"r"(b0),"r"(b1));
}
// cp.async fill of ROWSN x 64 (2-byte) tile into SW128 smem
template<int ROWSN, typename T>
__device__ __forceinline__ void cpfill(uint32_t s, const T* __restrict__ g, int ldK, int tid){
#pragma unroll
    for(int i=0;i<ROWSN/32;i++){
        int idx=tid+(i<<8); int r=idx>>3, c=idx&7;
        uint32_t dst=s+SWZ((unsigned)((r<<7)+(c<<4)));
        const void* src=g+(long)r*ldK+(c<<3);
        asm volatile("cp.async.cg.shared.global [%0], [%1], 16;"::"r"(dst),"l"(src):"memory");
    }
}

// ---- fp32 -> fp16 ----
__global__ __launch_bounds__(256) void tof16(const float* __restrict__ in, f16* __restrict__ out, long n){
    long i=((long)blockIdx.x*256+threadIdx.x)*4;
    if(i>=n) return;
    float4 v=*reinterpret_cast<const float4*>(in+i);
    __half2 a=__floats2half2_rn(v.x,v.y), b=__floats2half2_rn(v.z,v.w);
    *reinterpret_cast<uint2*>(out+i)=make_uint2(*reinterpret_cast<unsigned*>(&a),*reinterpret_cast<unsigned*>(&b));
}

// ---------------------------------------------------------------------------
// fp16 single-pass GEMM, cp.async double-buffered: C = A B^T (+bias)(+resid)
// Tile 128x128, BK=64, 8 warps (4m x 2n). Stage stride 32KB, 2 stages.
// ---------------------------------------------------------------------------
__global__ __launch_bounds__(256) void gemm_h(
    const f16* __restrict__ a16,const f16* __restrict__ b16,
    const float* __restrict__ bias,const float* __restrict__ resid,
    float* __restrict__ C,int K,int N)
{
    extern __shared__ char smem[];
    const uint32_t sb=smem_u32(smem);
    const int tid=threadIdx.x, wid=tid>>5, lane=tid&31;
    const int m0=blockIdx.y<<7, n0=blockIdx.x<<7;
    const int wm=(wid&3)<<5, wn=(wid>>2)<<6;
    const f16* A=a16+(long)m0*K;
    const f16* B=b16+(long)n0*K;
    const int NS=K>>6;

    cpfill<128>(sb,       A, K, tid);
    cpfill<128>(sb+16384, B, K, tid);
    CPCOMMIT();

    float acc[2][8][4]={};
    for(int s=0;s<NS;s++){
        if(s+1<NS){
            uint32_t st=sb+((s+1)&1)*32768;
            cpfill<128>(st,       A+(s+1)*64, K, tid);
            cpfill<128>(st+16384, B+(s+1)*64, K, tid);
            CPCOMMIT(); CPWAIT1();
        } else CPWAIT0();
        __syncthreads();
        const uint32_t sA=sb+(s&1)*32768, sB=sA+16384;
#pragma unroll
        for(int ks=0;ks<4;ks++){
            uint32_t av[2][4];
            ldm4(av[0], sA, wm,    ks, lane); ldm4(av[1], sA, wm+16, ks, lane);
            uint32_t bv[4][4];
#pragma unroll
            for(int j=0;j<4;j++) ldm4(bv[j], sB, wn+(j<<4), ks, lane);
#pragma unroll
            for(int mi=0;mi<2;mi++)
#pragma unroll
                for(int j=0;j<4;j++){
                    mma_hf(acc[mi][2*j],   av[mi], bv[j][0], bv[j][2]);
                    mma_hf(acc[mi][2*j+1], av[mi], bv[j][1], bv[j][3]);
                }
        }
        __syncthreads();
    }
#pragma unroll
    for(int mi=0;mi<2;mi++)
#pragma unroll
        for(int jj=0;jj<8;jj++){
            float* d=acc[mi][jj];
            int col=n0+wn+(jj<<3)+((lane&3)<<1);
            long row=m0+wm+(mi<<4)+(lane>>2);
            float2 v0=make_float2(d[0],d[1]), v1=make_float2(d[2],d[3]);
            if(bias){
                float2 bv=*reinterpret_cast<const float2*>(bias+col);
                v0.x+=bv.x; v0.y+=bv.y; v1.x+=bv.x; v1.y+=bv.y;
            }
            if(resid){
                float2 r0=*reinterpret_cast<const float2*>(resid+row*N+col);
                float2 r1=*reinterpret_cast<const float2*>(resid+(row+8)*N+col);
                v0.x+=r0.x; v0.y+=r0.y; v1.x+=r1.x; v1.y+=r1.y;
            }
            *reinterpret_cast<float2*>(C+row*N+col)=v0;
            *reinterpret_cast<float2*>(C+(row+8)*N+col)=v1;
        }
}

// ---- LN (no bias) -> fp16, scale folded ----
__global__ __launch_bounds__(256) void ln2f16(const float* __restrict__ in,const float* __restrict__ gamma,float scale,
                                              f16* __restrict__ o16){
    const long row=blockIdx.x; const float* p=in+row*DM; const int t=threadIdx.x;
    float v0=p[t],v1=p[t+256],v2=p[t+512];
    float s=v0+v1+v2, sq=v0*v0+v1*v1+v2*v2;
#pragma unroll
    for(int o=16;o;o>>=1){ s+=__shfl_xor_sync(~0u,s,o); sq+=__shfl_xor_sync(~0u,sq,o); }
    __shared__ float ss[8],sqs[8];
    int w=t>>5,ln=t&31;
    if(ln==0){ss[w]=s;sqs[w]=sq;} __syncthreads();
    if(w==0){ s=(ln<8)?ss[ln]:0.f; sq=(ln<8)?sqs[ln]:0.f;
#pragma unroll
        for(int o=4;o;o>>=1){ s+=__shfl_xor_sync(~0u,s,o); sq+=__shfl_xor_sync(~0u,sq,o); }
        if(ln==0){ss[0]=s;sqs[0]=sq;} }
    __syncthreads();
    float mu=ss[0]*(1.f/DM), var=sqs[0]*(1.f/DM)-mu*mu, rstd=rsqrtf(var+1e-5f)*scale;
#pragma unroll
    for(int g=0;g<3;g++){
        int c=t+g*256; float y=((g==0?v0:g==1?v1:v2)-mu)*rstd*gamma[c];
        o16[row*DM+c]=__float2half_rn(y);
    }
}

// ---------------------------------------------------------------------------
// Scores (single-pass fp16) + fused column sums; E = exp(s) fp16 (C=0).
// One k-slab (K=64). Tile 128x128, 8 warps.
// ---------------------------------------------------------------------------
__global__ __launch_bounds__(256) void scores_h(
    const f16* __restrict__ q16,const f16* __restrict__ k16,
    f16* __restrict__ E, float* __restrict__ psum)
{
    extern __shared__ char smem[];
    const uint32_t sb=smem_u32(smem);
    const uint32_t sA=sb, sB=sb+16384;
    const int tid=threadIdx.x, wid=tid>>5, lane=tid&31;
    const int z=blockIdx.z, b=z/NH, h=z-b*NH;
    const int m0=blockIdx.y<<7, n0=blockIdx.x<<7;
    const int wm=(wid&3)<<5, wn=(wid>>2)<<6;
    const f16* A=q16+(long)(b*SEQ+m0)*DM+h*HD;
    const f16* B=k16+(long)(b*SEQ+n0)*DM+h*HD;

    cpfill<128>(sA, A, DM, tid);
    cpfill<128>(sB, B, DM, tid);
    CPCOMMIT(); CPWAIT0();
    __syncthreads();

    float acc[2][8][4]={};
#pragma unroll
    for(int ks=0;ks<4;ks++){
        uint32_t av[2][4];
        ldm4(av[0], sA, wm,    ks, lane); ldm4(av[1], sA, wm+16, ks, lane);
        uint32_t bv[4][4];
#pragma unroll
        for(int j=0;j<4;j++) ldm4(bv[j], sB, wn+(j<<4), ks, lane);
#pragma unroll
        for(int mi=0;mi<2;mi++)
#pragma unroll
            for(int j=0;j<4;j++){
                mma_hf(acc[mi][2*j],   av[mi], bv[j][0], bv[j][2]);
                mma_hf(acc[mi][2*j+1], av[mi], bv[j][1], bv[j][3]);
            }
    }

    const long zoff=(long)z*SEQ*SEQ;
    float cs[8][2]={};
#pragma unroll
    for(int mi=0;mi<2;mi++)
#pragma unroll
        for(int jj=0;jj<8;jj++){
            float* d=acc[mi][jj];
            float e0=__expf(d[0]), e1=__expf(d[1]);
            float e2=__expf(d[2]), e3=__expf(d[3]);
            cs[jj][0]+=e0+e2; cs[jj][1]+=e1+e3;
            int col=n0+wn+(jj<<3)+((lane&3)<<1);
            long row=m0+wm+(mi<<4)+(lane>>2);
            __half2 p0=__floats2half2_rn(e0,e1), p1=__floats2half2_rn(e2,e3);
            *reinterpret_cast<unsigned*>(E+zoff+row*SEQ+col)=*reinterpret_cast<unsigned*>(&p0);
            *reinterpret_cast<unsigned*>(E+zoff+(row+8)*SEQ+col)=*reinterpret_cast<unsigned*>(&p1);
        }
    __shared__ float css[4][128];
#pragma unroll
    for(int jj=0;jj<8;jj++)
#pragma unroll
        for(int c=0;c<2;c++){
            float v=cs[jj][c];
            v+=__shfl_xor_sync(~0u,v,4); v+=__shfl_xor_sync(~0u,v,8); v+=__shfl_xor_sync(~0u,v,16);
            cs[jj][c]=v;
        }
    if(lane<4){
#pragma unroll
        for(int jj=0;jj<8;jj++){
            int cl=((wid>>2)<<6)+(jj<<3)+(lane<<1);
            css[wid&3][cl]  =cs[jj][0];
            css[wid&3][cl+1]=cs[jj][1];
        }
    }
    __syncthreads();
    if(tid<128){
        float p=css[0][tid]+css[1][tid]+css[2][tid]+css[3][tid];
        psum[((long)z*16+blockIdx.y)*SEQ + n0 + tid]=p;
    }
}

// ---- rsum[z][k] = 1 / sum_qb psum ----
__global__ __launch_bounds__(256) void rsum_k(const float* __restrict__ psum, float* __restrict__ rsum){
    int i=blockIdx.x*256+threadIdx.x;
    int z=i>>11, k=i&2047;
    float s=0.f;
#pragma unroll
    for(int qb=0;qb<16;qb++) s+=psum[((long)z*16+qb)*SEQ+k];
    rsum[i]=1.f/s;
}

// ---- v [8192][768] -> vt fp16 [z][64][2048], scaled by rsum[z][k] ----
__global__ void vtscale(const float* __restrict__ v, const float* __restrict__ rsum,
                        f16* __restrict__ vt){
    __shared__ float tile[32][33];
    int b=blockIdx.z, c0=blockIdx.y*32, t0=blockIdx.x*32;
    int tx=threadIdx.x, ty=threadIdx.y;
#pragma unroll
    for(int j=0;j<32;j+=8) tile[ty+j][tx]=v[(long)(b*SEQ+t0+ty+j)*DM+c0+tx];
    __syncthreads();
    int z=b*NH+(c0>>6), ch=c0&63;
    float rs=rsum[z*SEQ+t0+tx];
#pragma unroll
    for(int j=0;j<32;j+=8){
        long o=((long)z*HD+ch+ty+j)*SEQ+t0+tx;
        vt[o]=__float2half_rn(tile[tx][ty+j]*rs);
    }
}

// ---------------------------------------------------------------------------
// PV: fp16 GEMM, cp.async double-buffered. Stage stride 24KB, 2 stages.
// ---------------------------------------------------------------------------
__global__ __launch_bounds__(256) void pv_h(
    const f16* __restrict__ E,const f16* __restrict__ vt, f16* __restrict__ o16)
{
    extern __shared__ char smem[];
    const uint32_t sb=smem_u32(smem);
    const int tid=threadIdx.x, wid=tid>>5, lane=tid&31;
    const int z=blockIdx.y, b=z/NH, h=z-b*NH;
    const int q0=blockIdx.x<<7;
    const int wm=(wid&3)<<5, wn=(wid>>2)<<5;
    const f16* A=E+(long)z*SEQ*SEQ+(long)q0*SEQ;
    const f16* B=vt+(long)z*HD*SEQ;

    cpfill<128>(sb,       A, SEQ, tid);
    cpfill<64>(sb+16384,  B, SEQ, tid);
    CPCOMMIT();

    float acc[2][4][4]={};
    for(int s=0;s<32;s++){
        if(s+1<32){
            uint32_t st=sb+((s+1)&1)*24576;
            cpfill<128>(st,       A+(s+1)*64, SEQ, tid);
            cpfill<64>(st+16384,  B+(s+1)*64, SEQ, tid);
            CPCOMMIT(); CPWAIT1();
        } else CPWAIT0();
        __syncthreads();
        const uint32_t sA=sb+(s&1)*24576, sB=sA+16384;
#pragma unroll
        for(int ks=0;ks<4;ks++){
            uint32_t av[2][4];
            ldm4(av[0], sA, wm,    ks, lane); ldm4(av[1], sA, wm+16, ks, lane);
            uint32_t bv[2][4];
#pragma unroll
            for(int j=0;j<2;j++) ldm4(bv[j], sB, wn+(j<<4), ks, lane);
#pragma unroll
            for(int mi=0;mi<2;mi++)
#pragma unroll
                for(int j=0;j<2;j++){
                    mma_hf(acc[mi][2*j],   av[mi], bv[j][0], bv[j][2]);
                    mma_hf(acc[mi][2*j+1], av[mi], bv[j][1], bv[j][3]);
                }
        }
        __syncthreads();
    }
#pragma unroll
    for(int mi=0;mi<2;mi++)
#pragma unroll
        for(int jj=0;jj<4;jj++){
            float* d=acc[mi][jj];
            int col=h*HD+wn+(jj<<3)+((lane&3)<<1);
            long row=(long)b*SEQ+q0+wm+(mi<<4)+(lane>>2);
            __half2 p0=__floats2half2_rn(d[0],d[1]), p1=__floats2half2_rn(d[2],d[3]);
            *reinterpret_cast<unsigned*>(o16+row*DM+col)=*reinterpret_cast<unsigned*>(&p0);
            *reinterpret_cast<unsigned*>(o16+(row+8)*DM+col)=*reinterpret_cast<unsigned*>(&p1);
        }
}

extern "C" void kernel_launch(void* const* d_in, const int* in_sizes, int n_in,
                              void* d_out, int out_size)
{
    const float* x =(const float*)d_in[0];
    const float* Wq=(const float*)d_in[1];
    const float* Wk=(const float*)d_in[2];
    const float* bk=(const float*)d_in[3];
    const float* Wv=(const float*)d_in[4];
    const float* bv=(const float*)d_in[5];
    const float* gq=(const float*)d_in[6];
    const float* gk=(const float*)d_in[7];
    const float* Wo=(const float*)d_in[8];
    const float* bo=(const float*)d_in[9];
    float* out=(float*)d_out;

    f16 *x16,*w16,*q16,*k16,*vt,*E,*o16;
    float *q,*k,*v,*psum,*rsum;
    cudaGetSymbolAddress((void**)&x16,g_x16); cudaGetSymbolAddress((void**)&w16,g_w16);
    cudaGetSymbolAddress((void**)&q,g_q); cudaGetSymbolAddress((void**)&k,g_k);
    cudaGetSymbolAddress((void**)&v,g_v);
    cudaGetSymbolAddress((void**)&q16,g_q16); cudaGetSymbolAddress((void**)&k16,g_k16);
    cudaGetSymbolAddress((void**)&vt,g_vt);
    cudaGetSymbolAddress((void**)&E,g_E);
    cudaGetSymbolAddress((void**)&psum,g_psum); cudaGetSymbolAddress((void**)&rsum,g_rsum);
    cudaGetSymbolAddress((void**)&o16,g_o16);

    cudaFuncSetAttribute(gemm_h,   cudaFuncAttributeMaxDynamicSharedMemorySize, 65536);
    cudaFuncSetAttribute(scores_h, cudaFuncAttributeMaxDynamicSharedMemorySize, 32768);
    cudaFuncSetAttribute(pv_h,     cudaFuncAttributeMaxDynamicSharedMemorySize, 49152);

    const long NX=(long)ROWS*DM, NW=(long)DM*DM;
    tof16<<<NX/1024,256>>>(x, x16, NX);
    tof16<<<NW/1024,256>>>(Wq, w16+0*NW, NW);
    tof16<<<NW/1024,256>>>(Wk, w16+1*NW, NW);
    tof16<<<NW/1024,256>>>(Wv, w16+2*NW, NW);
    tof16<<<NW/1024,256>>>(Wo, w16+3*NW, NW);

    dim3 gp(DM/128, ROWS/128);
    gemm_h<<<gp,256,65536>>>(x16, w16+0*NW, nullptr, nullptr, q, DM, DM);
    gemm_h<<<gp,256,65536>>>(x16, w16+1*NW, bk,      nullptr, k, DM, DM);
    gemm_h<<<gp,256,65536>>>(x16, w16+2*NW, bv,      nullptr, v, DM, DM);

    ln2f16<<<ROWS,256>>>(q, gq, 0.125f, q16);
    ln2f16<<<ROWS,256>>>(k, gk, 1.0f,   k16);

    scores_h<<<dim3(SEQ/128, SEQ/128, ZBN),256,32768>>>(q16, k16, E, psum);
    rsum_k<<<ZBN*SEQ/256,256>>>(psum, rsum);
    vtscale<<<dim3(SEQ/32, DM/32, 4), dim3(32,8)>>>(v, rsum, vt);

    pv_h<<<dim3(SEQ/128, ZBN),256,24576*2>>>(E, vt, o16);

    gemm_h<<<gp,256,65536>>>(o16, w16+3*NW, bo, x, out, DM, DM);
}

// round 12
// speedup vs baseline: 5.6785x; 1.1197x over previous
#include <cuda_runtime.h>
#include <cuda_fp16.h>
#include <cstdint>

#define SEQ 2048
#define DM 768
#define NH 12
#define HD 64
#define ROWS 8192
#define ZBN 48
typedef __half f16;

// ---------------- scratch ----------------
__device__ __align__(16) f16  g_x16[ROWS*DM];
__device__ __align__(16) f16  g_w16[4][DM*DM];
__device__ __align__(16) float g_q[ROWS*DM], g_k[ROWS*DM], g_v[ROWS*DM];
__device__ __align__(16) f16  g_q16[ROWS*DM], g_k16[ROWS*DM];
__device__ __align__(16) f16  g_vt[(long)ZBN*HD*SEQ];
__device__ __align__(16) float g_rsum[ZBN*SEQ];
__device__ __align__(16) f16  g_o16[ROWS*DM];

#define SWZ(o) ((o)^(((o)>>3)&0x70))
#define CPCOMMIT() asm volatile("cp.async.commit_group;":::"memory")
#define CPWAIT1()  asm volatile("cp.async.wait_group 1;":::"memory")
#define CPWAIT0()  asm volatile("cp.async.wait_group 0;":::"memory")

__device__ __forceinline__ uint32_t smem_u32(const void* p){
    uint32_t a; asm("{ .reg .u64 t; cvta.to.shared.u64 t, %1; cvt.u32.u64 %0, t; }":"=r"(a):"l"(p)); return a;
}
__device__ __forceinline__ void ldm4(uint32_t* r, uint32_t base, int row0, int ks, int lane){
    uint32_t addr = base + SWZ((unsigned)((row0+(lane&15))<<7) + (unsigned)(((ks<<1)+(lane>>4))<<4));
    asm volatile("ldmatrix.sync.aligned.m8n8.x4.shared.b16 {%0,%1,%2,%3}, [%4];"
        :"=r"(r[0]),"=r"(r[1]),"=r"(r[2]),"=r"(r[3]):"r"(addr));
}
__device__ __forceinline__ void mma_hf(float* d, const uint32_t* a, uint32_t b0, uint32_t b1){
    asm volatile("mma.sync.aligned.m16n8k16.row.col.f32.f16.f16.f32 "
        "{%0,%1,%2,%3},{%4,%5,%6,%7},{%8,%9},{%0,%1,%2,%3};"
        : "+f"(d[0]),"+f"(d[1]),"+f"(d[2]),"+f"(d[3])
        : "r"(a[0]),"r"(a[1]),"r"(a[2]),"r"(a[3]),"r"(b0),"r"(b1));
}
__device__ __forceinline__ unsigned packexp(float a, float b){
    __half2 h=__floats2half2_rn(__expf(a),__expf(b));
    return *reinterpret_cast<unsigned*>(&h);
}
// cp.async fill of ROWSN x 64 (2-byte) tile into SW128 smem (256 threads)
template<int ROWSN, typename T>
__device__ __forceinline__ void cpfill(uint32_t s, const T* __restrict__ g, int ldK, int tid){
#pragma unroll
    for(int i=0;i<ROWSN/32;i++){
        int idx=tid+(i<<8); int r=idx>>3, c=idx&7;
        uint32_t dst=s+SWZ((unsigned)((r<<7)+(c<<4)));
        const void* src=g+(long)r*ldK+(c<<3);
        asm volatile("cp.async.cg.shared.global [%0], [%1], 16;"::"r"(dst),"l"(src):"memory");
    }
}

// ---- fp32 -> fp16 ----
__global__ __launch_bounds__(256) void tof16(const float* __restrict__ in, f16* __restrict__ out, long n){
    long i=((long)blockIdx.x*256+threadIdx.x)*4;
    if(i>=n) return;
    float4 v=*reinterpret_cast<const float4*>(in+i);
    __half2 a=__floats2half2_rn(v.x,v.y), b=__floats2half2_rn(v.z,v.w);
    *reinterpret_cast<uint2*>(out+i)=make_uint2(*reinterpret_cast<unsigned*>(&a),*reinterpret_cast<unsigned*>(&b));
}

// ---------------------------------------------------------------------------
// fp16 GEMM, cp.async double-buffered: C = A B^T (+bias)(+resid)
// ---------------------------------------------------------------------------
__global__ __launch_bounds__(256) void gemm_h(
    const f16* __restrict__ a16,const f16* __restrict__ b16,
    const float* __restrict__ bias,const float* __restrict__ resid,
    float* __restrict__ C,int K,int N)
{
    extern __shared__ char smem[];
    const uint32_t sb=smem_u32(smem);
    const int tid=threadIdx.x, wid=tid>>5, lane=tid&31;
    const int m0=blockIdx.y<<7, n0=blockIdx.x<<7;
    const int wm=(wid&3)<<5, wn=(wid>>2)<<6;
    const f16* A=a16+(long)m0*K;
    const f16* B=b16+(long)n0*K;
    const int NS=K>>6;

    cpfill<128>(sb,       A, K, tid);
    cpfill<128>(sb+16384, B, K, tid);
    CPCOMMIT();

    float acc[2][8][4]={};
    for(int s=0;s<NS;s++){
        if(s+1<NS){
            uint32_t st=sb+((s+1)&1)*32768;
            cpfill<128>(st,       A+(s+1)*64, K, tid);
            cpfill<128>(st+16384, B+(s+1)*64, K, tid);
            CPCOMMIT(); CPWAIT1();
        } else CPWAIT0();
        __syncthreads();
        const uint32_t sA=sb+(s&1)*32768, sB=sA+16384;
#pragma unroll
        for(int ks=0;ks<4;ks++){
            uint32_t av[2][4];
            ldm4(av[0], sA, wm,    ks, lane); ldm4(av[1], sA, wm+16, ks, lane);
            uint32_t bv[4][4];
#pragma unroll
            for(int j=0;j<4;j++) ldm4(bv[j], sB, wn+(j<<4), ks, lane);
#pragma unroll
            for(int mi=0;mi<2;mi++)
#pragma unroll
                for(int j=0;j<4;j++){
                    mma_hf(acc[mi][2*j],   av[mi], bv[j][0], bv[j][2]);
                    mma_hf(acc[mi][2*j+1], av[mi], bv[j][1], bv[j][3]);
                }
        }
        __syncthreads();
    }
#pragma unroll
    for(int mi=0;mi<2;mi++)
#pragma unroll
        for(int jj=0;jj<8;jj++){
            float* d=acc[mi][jj];
            int col=n0+wn+(jj<<3)+((lane&3)<<1);
            long row=m0+wm+(mi<<4)+(lane>>2);
            float2 v0=make_float2(d[0],d[1]), v1=make_float2(d[2],d[3]);
            if(bias){
                float2 bv=*reinterpret_cast<const float2*>(bias+col);
                v0.x+=bv.x; v0.y+=bv.y; v1.x+=bv.x; v1.y+=bv.y;
            }
            if(resid){
                float2 r0=*reinterpret_cast<const float2*>(resid+row*N+col);
                float2 r1=*reinterpret_cast<const float2*>(resid+(row+8)*N+col);
                v0.x+=r0.x; v0.y+=r0.y; v1.x+=r1.x; v1.y+=r1.y;
            }
            *reinterpret_cast<float2*>(C+row*N+col)=v0;
            *reinterpret_cast<float2*>(C+(row+8)*N+col)=v1;
        }
}

// ---- LN (no bias) -> fp16, scale folded ----
__global__ __launch_bounds__(256) void ln2f16(const float* __restrict__ in,const float* __restrict__ gamma,float scale,
                                              f16* __restrict__ o16){
    const long row=blockIdx.x; const float* p=in+row*DM; const int t=threadIdx.x;
    float v0=p[t],v1=p[t+256],v2=p[t+512];
    float s=v0+v1+v2, sq=v0*v0+v1*v1+v2*v2;
#pragma unroll
    for(int o=16;o;o>>=1){ s+=__shfl_xor_sync(~0u,s,o); sq+=__shfl_xor_sync(~0u,sq,o); }
    __shared__ float ss[8],sqs[8];
    int w=t>>5,ln=t&31;
    if(ln==0){ss[w]=s;sqs[w]=sq;} __syncthreads();
    if(w==0){ s=(ln<8)?ss[ln]:0.f; sq=(ln<8)?sqs[ln]:0.f;
#pragma unroll
        for(int o=4;o;o>>=1){ s+=__shfl_xor_sync(~0u,s,o); sq+=__shfl_xor_sync(~0u,sq,o); }
        if(ln==0){ss[0]=s;sqs[0]=sq;} }
    __syncthreads();
    float mu=ss[0]*(1.f/DM), var=sqs[0]*(1.f/DM)-mu*mu, rstd=rsqrtf(var+1e-5f)*scale;
#pragma unroll
    for(int g=0;g<3;g++){
        int c=t+g*256; float y=((g==0?v0:g==1?v1:v2)-mu)*rstd*gamma[c];
        o16[row*DM+c]=__float2half_rn(y);
    }
}

// ---------------------------------------------------------------------------
// Pass 1: rsum[z][k] = 1/sum_q exp(S). CTA = (z, k-tile 128); K-tile resident,
// streams 16 q-slabs (128 q each). S^T computed (m=kv, n=q), exp row-summed.
// ---------------------------------------------------------------------------
__global__ __launch_bounds__(256) void colsum_h(
    const f16* __restrict__ q16,const f16* __restrict__ k16, float* __restrict__ rsum)
{
    extern __shared__ char smem[];
    const uint32_t sb=smem_u32(smem);
    const int tid=threadIdx.x, wid=tid>>5, lane=tid&31;
    const int z=blockIdx.y, b=z/NH, h=z-b*NH;
    const int k0=blockIdx.x<<7;
    const int wm=(wid&3)<<5, wng=wid>>2;
    const f16* Kp=k16+(long)(b*SEQ+k0)*DM+h*HD;
    const f16* Qp=q16+(long)(b*SEQ)*DM+h*HD;

    // K tile + first q slab
    cpfill<128>(sb, Kp, DM, tid);
    cpfill<128>(sb+16384, Qp, DM, tid);
    CPCOMMIT(); CPWAIT0();
    __syncthreads();

    uint32_t ka[2][4][4];
#pragma unroll
    for(int mi=0;mi<2;mi++)
#pragma unroll
        for(int ks=0;ks<4;ks++) ldm4(ka[mi][ks], sb, wm+(mi<<4), ks, lane);

    float rs[2][2]={};
    for(int s=0;s<16;s++){
        if(s+1<16){
            cpfill<128>(sb+16384+((s+1)&1)*16384, Qp+(long)(s+1)*128*DM, DM, tid);
            CPCOMMIT(); CPWAIT1();
        } else CPWAIT0();
        __syncthreads();
        const uint32_t sQ=sb+16384+(s&1)*16384;
        float acc[2][8][4]={};
#pragma unroll
        for(int ks=0;ks<4;ks++){
            uint32_t bv[4][4];
#pragma unroll
            for(int j=0;j<4;j++) ldm4(bv[j], sQ, (wng<<6)+(j<<4), ks, lane);
#pragma unroll
            for(int mi=0;mi<2;mi++)
#pragma unroll
                for(int j=0;j<4;j++){
                    mma_hf(acc[mi][2*j],   ka[mi][ks], bv[j][0], bv[j][2]);
                    mma_hf(acc[mi][2*j+1], ka[mi][ks], bv[j][1], bv[j][3]);
                }
        }
#pragma unroll
        for(int mi=0;mi<2;mi++)
#pragma unroll
            for(int jj=0;jj<8;jj++){
                float* d=acc[mi][jj];
                rs[mi][0]+=__expf(d[0])+__expf(d[1]);
                rs[mi][1]+=__expf(d[2])+__expf(d[3]);
            }
        __syncthreads();
    }
    // reduce over lane quad (cols) then across the 2 q-groups
    __shared__ float cs[2][128];
#pragma unroll
    for(int mi=0;mi<2;mi++)
#pragma unroll
        for(int p=0;p<2;p++){
            float v=rs[mi][p];
            v+=__shfl_xor_sync(~0u,v,1); v+=__shfl_xor_sync(~0u,v,2);
            if((lane&3)==0) cs[wng][wm+(mi<<4)+(p<<3)+(lane>>2)]=v;
        }
    __syncthreads();
    if(tid<128){
        float s=cs[0][tid]+cs[1][tid];
        rsum[(long)z*SEQ+k0+tid]=1.f/s;
    }
}

// ---- v [8192][768] -> vt fp16 [z][64][2048], scaled by rsum[z][k] ----
__global__ void vtscale(const float* __restrict__ v, const float* __restrict__ rsum,
                        f16* __restrict__ vt){
    __shared__ float tile[32][33];
    int b=blockIdx.z, c0=blockIdx.y*32, t0=blockIdx.x*32;
    int tx=threadIdx.x, ty=threadIdx.y;
#pragma unroll
    for(int j=0;j<32;j+=8) tile[ty+j][tx]=v[(long)(b*SEQ+t0+ty+j)*DM+c0+tx];
    __syncthreads();
    int z=b*NH+(c0>>6), ch=c0&63;
    float rs=rsum[z*SEQ+t0+tx];
#pragma unroll
    for(int j=0;j<32;j+=8){
        long o=((long)z*HD+ch+ty+j)*SEQ+t0+tx;
        vt[o]=__float2half_rn(tile[tx][ty+j]*rs);
    }
}

// ---------------------------------------------------------------------------
// Pass 2: fused scores+PV (flash-style). CTA = (z, q-tile 128); Q fragments in
// registers; loop 32 k-slabs: S = Q K^T, P = exp(S) packed c->a in registers,
// O += P V'. V' = V * rsum (pre-scaled). E never hits DRAM.
// ---------------------------------------------------------------------------
__global__ __launch_bounds__(256) void flashpv_h(
    const f16* __restrict__ q16,const f16* __restrict__ k16,
    const f16* __restrict__ vt, f16* __restrict__ o16)
{
    extern __shared__ char smem[];
    const uint32_t sb=smem_u32(smem);
    const int tid=threadIdx.x, wid=tid>>5, lane=tid&31;
    const int z=blockIdx.y, b=z/NH, h=z-b*NH;
    const int q0=blockIdx.x<<7;
    const int wq=wid<<4;
    const f16* Qp=q16+(long)(b*SEQ+q0)*DM+h*HD;
    const f16* Kp=k16+(long)(b*SEQ)*DM+h*HD;
    const f16* Vp=vt+(long)z*HD*SEQ;

    // Q tile + first k/v slab
    cpfill<128>(sb, Qp, DM, tid);
    {
        uint32_t st=sb+16384;
        cpfill<64>(st,      Kp, DM, tid);
        cpfill<64>(st+8192, Vp, SEQ, tid);
    }
    CPCOMMIT(); CPWAIT0();
    __syncthreads();

    uint32_t qa[4][4];
#pragma unroll
    for(int ks=0;ks<4;ks++) ldm4(qa[ks], sb, wq, ks, lane);

    float accp[8][4]={};
    for(int s=0;s<32;s++){
        if(s+1<32){
            uint32_t st=sb+16384+((s+1)&1)*16384;
            cpfill<64>(st,      Kp+(long)(s+1)*64*DM, DM, tid);
            cpfill<64>(st+8192, Vp+(s+1)*64, SEQ, tid);
            CPCOMMIT(); CPWAIT1();
        } else CPWAIT0();
        __syncthreads();
        const uint32_t sK=sb+16384+(s&1)*16384, sV=sK+8192;

        float accs[8][4]={};
#pragma unroll
        for(int ks=0;ks<4;ks++){
            uint32_t bv[4][4];
#pragma unroll
            for(int j=0;j<4;j++) ldm4(bv[j], sK, j<<4, ks, lane);
#pragma unroll
            for(int j=0;j<4;j++){
                mma_hf(accs[2*j],   qa[ks], bv[j][0], bv[j][2]);
                mma_hf(accs[2*j+1], qa[ks], bv[j][1], bv[j][3]);
            }
        }
        // P = exp(S): pack c-layout -> a-layout fragments (FA2 identity)
        uint32_t pa[4][4];
#pragma unroll
        for(int g=0;g<4;g++){
            float* cl=accs[2*g]; float* ch=accs[2*g+1];
            pa[g][0]=packexp(cl[0],cl[1]);
            pa[g][1]=packexp(cl[2],cl[3]);
            pa[g][2]=packexp(ch[0],ch[1]);
            pa[g][3]=packexp(ch[2],ch[3]);
        }
        // O += P V'
#pragma unroll
        for(int g=0;g<4;g++){
            uint32_t bv[4][4];
#pragma unroll
            for(int j=0;j<4;j++) ldm4(bv[j], sV, j<<4, g, lane);
#pragma unroll
            for(int j=0;j<4;j++){
                mma_hf(accp[2*j],   pa[g], bv[j][0], bv[j][2]);
                mma_hf(accp[2*j+1], pa[g], bv[j][1], bv[j][3]);
            }
        }
        __syncthreads();
    }
#pragma unroll
    for(int jj=0;jj<8;jj++){
        float* d=accp[jj];
        int col=h*HD+(jj<<3)+((lane&3)<<1);
        long row=(long)b*SEQ+q0+wq+(lane>>2);
        __half2 p0=__floats2half2_rn(d[0],d[1]), p1=__floats2half2_rn(d[2],d[3]);
        *reinterpret_cast<unsigned*>(o16+row*DM+col)=*reinterpret_cast<unsigned*>(&p0);
        *reinterpret_cast<unsigned*>(o16+(row+8)*DM+col)=*reinterpret_cast<unsigned*>(&p1);
    }
}

extern "C" void kernel_launch(void* const* d_in, const int* in_sizes, int n_in,
                              void* d_out, int out_size)
{
    const float* x =(const float*)d_in[0];
    const float* Wq=(const float*)d_in[1];
    const float* Wk=(const float*)d_in[2];
    const float* bk=(const float*)d_in[3];
    const float* Wv=(const float*)d_in[4];
    const float* bv=(const float*)d_in[5];
    const float* gq=(const float*)d_in[6];
    const float* gk=(const float*)d_in[7];
    const float* Wo=(const float*)d_in[8];
    const float* bo=(const float*)d_in[9];
    float* out=(float*)d_out;

    f16 *x16,*w16,*q16,*k16,*vt,*o16;
    float *q,*k,*v,*rsum;
    cudaGetSymbolAddress((void**)&x16,g_x16); cudaGetSymbolAddress((void**)&w16,g_w16);
    cudaGetSymbolAddress((void**)&q,g_q); cudaGetSymbolAddress((void**)&k,g_k);
    cudaGetSymbolAddress((void**)&v,g_v);
    cudaGetSymbolAddress((void**)&q16,g_q16); cudaGetSymbolAddress((void**)&k16,g_k16);
    cudaGetSymbolAddress((void**)&vt,g_vt);
    cudaGetSymbolAddress((void**)&rsum,g_rsum);
    cudaGetSymbolAddress((void**)&o16,g_o16);

    cudaFuncSetAttribute(gemm_h,    cudaFuncAttributeMaxDynamicSharedMemorySize, 65536);
    cudaFuncSetAttribute(colsum_h,  cudaFuncAttributeMaxDynamicSharedMemorySize, 49152);
    cudaFuncSetAttribute(flashpv_h, cudaFuncAttributeMaxDynamicSharedMemorySize, 49152);

    const long NX=(long)ROWS*DM, NW=(long)DM*DM;
    tof16<<<NX/1024,256>>>(x, x16, NX);
    tof16<<<NW/1024,256>>>(Wq, w16+0*NW, NW);
    tof16<<<NW/1024,256>>>(Wk, w16+1*NW, NW);
    tof16<<<NW/1024,256>>>(Wv, w16+2*NW, NW);
    tof16<<<NW/1024,256>>>(Wo, w16+3*NW, NW);

    dim3 gp(DM/128, ROWS/128);
    gemm_h<<<gp,256,65536>>>(x16, w16+0*NW, nullptr, nullptr, q, DM, DM);
    gemm_h<<<gp,256,65536>>>(x16, w16+1*NW, bk,      nullptr, k, DM, DM);
    gemm_h<<<gp,256,65536>>>(x16, w16+2*NW, bv,      nullptr, v, DM, DM);

    ln2f16<<<ROWS,256>>>(q, gq, 0.125f, q16);
    ln2f16<<<ROWS,256>>>(k, gk, 1.0f,   k16);

    colsum_h<<<dim3(SEQ/128, ZBN),256,49152>>>(q16, k16, rsum);
    vtscale<<<dim3(SEQ/32, DM/32, 4), dim3(32,8)>>>(v, rsum, vt);
    flashpv_h<<<dim3(SEQ/128, ZBN),256,49152>>>(q16, k16, vt, o16);

    gemm_h<<<gp,256,65536>>>(o16, w16+3*NW, bo, x, out, DM, DM);
}

// round 13
// speedup vs baseline: 5.8714x; 1.0340x over previous
#include <cuda_runtime.h>
#include <cuda_fp16.h>
#include <cstdint>

#define SEQ 2048
#define DM 768
#define NH 12
#define HD 64
#define ROWS 8192
#define ZBN 48
#define NQKV 2304
typedef __half f16;

// ---------------- scratch ----------------
__device__ __align__(16) f16  g_x16[ROWS*DM];
__device__ __align__(16) f16  g_w16[4][DM*DM];     // Wq,Wk,Wv contiguous -> [2304x768]; Wo at [3]
__device__ __align__(16) float g_biasqkv[NQKV];
__device__ __align__(16) float g_qkv[(long)ROWS*NQKV];
__device__ __align__(16) f16  g_q16[ROWS*DM], g_k16[ROWS*DM];
__device__ __align__(16) f16  g_vt[(long)ZBN*HD*SEQ];
__device__ __align__(16) float g_rsum[ZBN*SEQ];
__device__ __align__(16) f16  g_o16[ROWS*DM];

#define SWZ(o) ((o)^(((o)>>3)&0x70))
#define CPCOMMIT() asm volatile("cp.async.commit_group;":::"memory")
#define CPWAIT1()  asm volatile("cp.async.wait_group 1;":::"memory")
#define CPWAIT0()  asm volatile("cp.async.wait_group 0;":::"memory")

__device__ __forceinline__ uint32_t smem_u32(const void* p){
    uint32_t a; asm("{ .reg .u64 t; cvta.to.shared.u64 t, %1; cvt.u32.u64 %0, t; }":"=r"(a):"l"(p)); return a;
}
__device__ __forceinline__ void ldm4(uint32_t* r, uint32_t base, int row0, int ks, int lane){
    uint32_t addr = base + SWZ((unsigned)((row0+(lane&15))<<7) + (unsigned)(((ks<<1)+(lane>>4))<<4));
    asm volatile("ldmatrix.sync.aligned.m8n8.x4.shared.b16 {%0,%1,%2,%3}, [%4];"
        :"=r"(r[0]),"=r"(r[1]),"=r"(r[2]),"=r"(r[3]):"r"(addr));
}
__device__ __forceinline__ void mma_hf(float* d, const uint32_t* a, uint32_t b0, uint32_t b1){
    asm volatile("mma.sync.aligned.m16n8k16.row.col.f32.f16.f16.f32 "
        "{%0,%1,%2,%3},{%4,%5,%6,%7},{%8,%9},{%0,%1,%2,%3};"
        : "+f"(d[0]),"+f"(d[1]),"+f"(d[2]),"+f"(d[3])
        : "r"(a[0]),"r"(a[1]),"r"(a[2]),"r"(a[3]),"r"(b0),"r"(b1));
}
__device__ __forceinline__ unsigned packexp(float a, float b){
    __half2 h=__floats2half2_rn(__expf(a),__expf(b));
    return *reinterpret_cast<unsigned*>(&h);
}
template<int ROWSN, typename T>
__device__ __forceinline__ void cpfill(uint32_t s, const T* __restrict__ g, int ldK, int tid){
#pragma unroll
    for(int i=0;i<ROWSN/32;i++){
        int idx=tid+(i<<8); int r=idx>>3, c=idx&7;
        uint32_t dst=s+SWZ((unsigned)((r<<7)+(c<<4)));
        const void* src=g+(long)r*ldK+(c<<3);
        asm volatile("cp.async.cg.shared.global [%0], [%1], 16;"::"r"(dst),"l"(src):"memory");
    }
}

// ---------------------------------------------------------------------------
// prep: all fp32->fp16 conversions + bias concat in one launch.
// grid (6144, 5): y=0..3 -> Wq,Wk,Wv,Wo (NW elems each), y=4 -> x (NX elems).
// ---------------------------------------------------------------------------
__global__ __launch_bounds__(256) void prep(
    const float* __restrict__ x,
    const float* __restrict__ Wq,const float* __restrict__ Wk,
    const float* __restrict__ Wv,const float* __restrict__ Wo,
    const float* __restrict__ bk,const float* __restrict__ bv,
    f16* __restrict__ x16, f16* __restrict__ w16, float* __restrict__ biasqkv)
{
    const long NX=(long)ROWS*DM, NW=(long)DM*DM;
    int y=blockIdx.y;
    long i=((long)blockIdx.x*256+threadIdx.x)*4;
    const float* src; f16* dst; long n;
    if(y==4){ src=x; dst=x16; n=NX; }
    else { src=(y==0)?Wq:(y==1)?Wk:(y==2)?Wv:Wo; dst=w16+(long)y*NW; n=NW; }
    if(i<n){
        float4 v=*reinterpret_cast<const float4*>(src+i);
        __half2 a=__floats2half2_rn(v.x,v.y), b=__floats2half2_rn(v.z,v.w);
        *reinterpret_cast<uint2*>(dst+i)=make_uint2(*reinterpret_cast<unsigned*>(&a),*reinterpret_cast<unsigned*>(&b));
    }
    if(y==0){
        int j=blockIdx.x*256+threadIdx.x;
        if(j<NQKV) biasqkv[j]=(j<DM)?0.f:((j<2*DM)?bk[j-DM]:bv[j-2*DM]);
    }
}

// ---------------------------------------------------------------------------
// fp16 GEMM, cp.async double-buffered: C = A B^T (+bias)(+resid)
// ---------------------------------------------------------------------------
__global__ __launch_bounds__(256) void gemm_h(
    const f16* __restrict__ a16,const f16* __restrict__ b16,
    const float* __restrict__ bias,const float* __restrict__ resid,
    float* __restrict__ C,int K,int N)
{
    extern __shared__ char smem[];
    const uint32_t sb=smem_u32(smem);
    const int tid=threadIdx.x, wid=tid>>5, lane=tid&31;
    const int m0=blockIdx.y<<7, n0=blockIdx.x<<7;
    const int wm=(wid&3)<<5, wn=(wid>>2)<<6;
    const f16* A=a16+(long)m0*K;
    const f16* B=b16+(long)n0*K;
    const int NS=K>>6;

    cpfill<128>(sb,       A, K, tid);
    cpfill<128>(sb+16384, B, K, tid);
    CPCOMMIT();

    float acc[2][8][4]={};
    for(int s=0;s<NS;s++){
        if(s+1<NS){
            uint32_t st=sb+((s+1)&1)*32768;
            cpfill<128>(st,       A+(s+1)*64, K, tid);
            cpfill<128>(st+16384, B+(s+1)*64, K, tid);
            CPCOMMIT(); CPWAIT1();
        } else CPWAIT0();
        __syncthreads();
        const uint32_t sA=sb+(s&1)*32768, sB=sA+16384;
#pragma unroll
        for(int ks=0;ks<4;ks++){
            uint32_t av[2][4];
            ldm4(av[0], sA, wm,    ks, lane); ldm4(av[1], sA, wm+16, ks, lane);
            uint32_t bv[4][4];
#pragma unroll
            for(int j=0;j<4;j++) ldm4(bv[j], sB, wn+(j<<4), ks, lane);
#pragma unroll
            for(int mi=0;mi<2;mi++)
#pragma unroll
                for(int j=0;j<4;j++){
                    mma_hf(acc[mi][2*j],   av[mi], bv[j][0], bv[j][2]);
                    mma_hf(acc[mi][2*j+1], av[mi], bv[j][1], bv[j][3]);
                }
        }
        __syncthreads();
    }
#pragma unroll
    for(int mi=0;mi<2;mi++)
#pragma unroll
        for(int jj=0;jj<8;jj++){
            float* d=acc[mi][jj];
            int col=n0+wn+(jj<<3)+((lane&3)<<1);
            long row=m0+wm+(mi<<4)+(lane>>2);
            float2 v0=make_float2(d[0],d[1]), v1=make_float2(d[2],d[3]);
            if(bias){
                float2 bv=*reinterpret_cast<const float2*>(bias+col);
                v0.x+=bv.x; v0.y+=bv.y; v1.x+=bv.x; v1.y+=bv.y;
            }
            if(resid){
                float2 r0=*reinterpret_cast<const float2*>(resid+row*N+col);
                float2 r1=*reinterpret_cast<const float2*>(resid+(row+8)*N+col);
                v0.x+=r0.x; v0.y+=r0.y; v1.x+=r1.x; v1.y+=r1.y;
            }
            *reinterpret_cast<float2*>(C+row*N+col)=v0;
            *reinterpret_cast<float2*>(C+(row+8)*N+col)=v1;
        }
}

// ---- LN (no bias) -> fp16; grid (ROWS, 2): y=0 -> q (scale .125), y=1 -> k ----
__global__ __launch_bounds__(256) void ln2f16(
    const float* __restrict__ qkv, const float* __restrict__ gq, const float* __restrict__ gk,
    f16* __restrict__ q16, f16* __restrict__ k16)
{
    const int y=blockIdx.y;
    const long row=blockIdx.x;
    const float* p=qkv+row*NQKV+(y?DM:0);
    const float* gamma=y?gk:gq;
    const float scale=y?1.0f:0.125f;
    f16* out=(y?k16:q16)+row*DM;
    const int t=threadIdx.x;

    float v0=p[t],v1=p[t+256],v2=p[t+512];
    float s=v0+v1+v2, sq=v0*v0+v1*v1+v2*v2;
#pragma unroll
    for(int o=16;o;o>>=1){ s+=__shfl_xor_sync(~0u,s,o); sq+=__shfl_xor_sync(~0u,sq,o); }
    __shared__ float ss[8],sqs[8];
    int w=t>>5,ln=t&31;
    if(ln==0){ss[w]=s;sqs[w]=sq;} __syncthreads();
    if(w==0){ s=(ln<8)?ss[ln]:0.f; sq=(ln<8)?sqs[ln]:0.f;
#pragma unroll
        for(int o=4;o;o>>=1){ s+=__shfl_xor_sync(~0u,s,o); sq+=__shfl_xor_sync(~0u,sq,o); }
        if(ln==0){ss[0]=s;sqs[0]=sq;} }
    __syncthreads();
    float mu=ss[0]*(1.f/DM), var=sqs[0]*(1.f/DM)-mu*mu, rstd=rsqrtf(var+1e-5f)*scale;
#pragma unroll
    for(int g=0;g<3;g++){
        int c=t+g*256; float yv=((g==0?v0:g==1?v1:v2)-mu)*rstd*gamma[c];
        out[c]=__float2half_rn(yv);
    }
}

// ---------------------------------------------------------------------------
// Pass 1: rsum[z][k] = 1/sum_q exp(S). CTA = (z, k-tile 128); K-tile resident.
// ---------------------------------------------------------------------------
__global__ __launch_bounds__(256) void colsum_h(
    const f16* __restrict__ q16,const f16* __restrict__ k16, float* __restrict__ rsum)
{
    extern __shared__ char smem[];
    const uint32_t sb=smem_u32(smem);
    const int tid=threadIdx.x, wid=tid>>5, lane=tid&31;
    const int z=blockIdx.y, b=z/NH, h=z-b*NH;
    const int k0=blockIdx.x<<7;
    const int wm=(wid&3)<<5, wng=wid>>2;
    const f16* Kp=k16+(long)(b*SEQ+k0)*DM+h*HD;
    const f16* Qp=q16+(long)(b*SEQ)*DM+h*HD;

    cpfill<128>(sb, Kp, DM, tid);
    cpfill<128>(sb+16384, Qp, DM, tid);
    CPCOMMIT(); CPWAIT0();
    __syncthreads();

    uint32_t ka[2][4][4];
#pragma unroll
    for(int mi=0;mi<2;mi++)
#pragma unroll
        for(int ks=0;ks<4;ks++) ldm4(ka[mi][ks], sb, wm+(mi<<4), ks, lane);

    float rs[2][2]={};
    for(int s=0;s<16;s++){
        if(s+1<16){
            cpfill<128>(sb+16384+((s+1)&1)*16384, Qp+(long)(s+1)*128*DM, DM, tid);
            CPCOMMIT(); CPWAIT1();
        } else CPWAIT0();
        __syncthreads();
        const uint32_t sQ=sb+16384+(s&1)*16384;
        float acc[2][8][4]={};
#pragma unroll
        for(int ks=0;ks<4;ks++){
            uint32_t bv[4][4];
#pragma unroll
            for(int j=0;j<4;j++) ldm4(bv[j], sQ, (wng<<6)+(j<<4), ks, lane);
#pragma unroll
            for(int mi=0;mi<2;mi++)
#pragma unroll
                for(int j=0;j<4;j++){
                    mma_hf(acc[mi][2*j],   ka[mi][ks], bv[j][0], bv[j][2]);
                    mma_hf(acc[mi][2*j+1], ka[mi][ks], bv[j][1], bv[j][3]);
                }
        }
#pragma unroll
        for(int mi=0;mi<2;mi++)
#pragma unroll
            for(int jj=0;jj<8;jj++){
                float* d=acc[mi][jj];
                rs[mi][0]+=__expf(d[0])+__expf(d[1]);
                rs[mi][1]+=__expf(d[2])+__expf(d[3]);
            }
        __syncthreads();
    }
    __shared__ float cs[2][128];
#pragma unroll
    for(int mi=0;mi<2;mi++)
#pragma unroll
        for(int p=0;p<2;p++){
            float v=rs[mi][p];
            v+=__shfl_xor_sync(~0u,v,1); v+=__shfl_xor_sync(~0u,v,2);
            if((lane&3)==0) cs[wng][wm+(mi<<4)+(p<<3)+(lane>>2)]=v;
        }
    __syncthreads();
    if(tid<128){
        float s=cs[0][tid]+cs[1][tid];
        rsum[(long)z*SEQ+k0+tid]=1.f/s;
    }
}

// ---- qkv v-part [8192][2304]@1536 -> vt fp16 [z][64][2048], scaled by rsum ----
__global__ void vtscale(const float* __restrict__ qkv, const float* __restrict__ rsum,
                        f16* __restrict__ vt){
    __shared__ float tile[32][33];
    int b=blockIdx.z, c0=blockIdx.y*32, t0=blockIdx.x*32;
    int tx=threadIdx.x, ty=threadIdx.y;
#pragma unroll
    for(int j=0;j<32;j+=8)
        tile[ty+j][tx]=qkv[(long)(b*SEQ+t0+ty+j)*NQKV+2*DM+c0+tx];
    __syncthreads();
    int z=b*NH+(c0>>6), ch=c0&63;
    float rs=rsum[z*SEQ+t0+tx];
#pragma unroll
    for(int j=0;j<32;j+=8){
        long o=((long)z*HD+ch+ty+j)*SEQ+t0+tx;
        vt[o]=__float2half_rn(tile[tx][ty+j]*rs);
    }
}

// ---------------------------------------------------------------------------
// Pass 2: fused scores+PV (flash-style), E never hits DRAM.
// ---------------------------------------------------------------------------
__global__ __launch_bounds__(256) void flashpv_h(
    const f16* __restrict__ q16,const f16* __restrict__ k16,
    const f16* __restrict__ vt, f16* __restrict__ o16)
{
    extern __shared__ char smem[];
    const uint32_t sb=smem_u32(smem);
    const int tid=threadIdx.x, wid=tid>>5, lane=tid&31;
    const int z=blockIdx.y, b=z/NH, h=z-b*NH;
    const int q0=blockIdx.x<<7;
    const int wq=wid<<4;
    const f16* Qp=q16+(long)(b*SEQ+q0)*DM+h*HD;
    const f16* Kp=k16+(long)(b*SEQ)*DM+h*HD;
    const f16* Vp=vt+(long)z*HD*SEQ;

    cpfill<128>(sb, Qp, DM, tid);
    {
        uint32_t st=sb+16384;
        cpfill<64>(st,      Kp, DM, tid);
        cpfill<64>(st+8192, Vp, SEQ, tid);
    }
    CPCOMMIT(); CPWAIT0();
    __syncthreads();

    uint32_t qa[4][4];
#pragma unroll
    for(int ks=0;ks<4;ks++) ldm4(qa[ks], sb, wq, ks, lane);

    float accp[8][4]={};
    for(int s=0;s<32;s++){
        if(s+1<32){
            uint32_t st=sb+16384+((s+1)&1)*16384;
            cpfill<64>(st,      Kp+(long)(s+1)*64*DM, DM, tid);
            cpfill<64>(st+8192, Vp+(s+1)*64, SEQ, tid);
            CPCOMMIT(); CPWAIT1();
        } else CPWAIT0();
        __syncthreads();
        const uint32_t sK=sb+16384+(s&1)*16384, sV=sK+8192;

        float accs[8][4]={};
#pragma unroll
        for(int ks=0;ks<4;ks++){
            uint32_t bv[4][4];
#pragma unroll
            for(int j=0;j<4;j++) ldm4(bv[j], sK, j<<4, ks, lane);
#pragma unroll
            for(int j=0;j<4;j++){
                mma_hf(accs[2*j],   qa[ks], bv[j][0], bv[j][2]);
                mma_hf(accs[2*j+1], qa[ks], bv[j][1], bv[j][3]);
            }
        }
        uint32_t pa[4][4];
#pragma unroll
        for(int g=0;g<4;g++){
            float* cl=accs[2*g]; float* ch=accs[2*g+1];
            pa[g][0]=packexp(cl[0],cl[1]);
            pa[g][1]=packexp(cl[2],cl[3]);
            pa[g][2]=packexp(ch[0],ch[1]);
            pa[g][3]=packexp(ch[2],ch[3]);
        }
#pragma unroll
        for(int g=0;g<4;g++){
            uint32_t bv[4][4];
#pragma unroll
            for(int j=0;j<4;j++) ldm4(bv[j], sV, j<<4, g, lane);
#pragma unroll
            for(int j=0;j<4;j++){
                mma_hf(accp[2*j],   pa[g], bv[j][0], bv[j][2]);
                mma_hf(accp[2*j+1], pa[g], bv[j][1], bv[j][3]);
            }
        }
        __syncthreads();
    }
#pragma unroll
    for(int jj=0;jj<8;jj++){
        float* d=accp[jj];
        int col=h*HD+(jj<<3)+((lane&3)<<1);
        long row=(long)b*SEQ+q0+wq+(lane>>2);
        __half2 p0=__floats2half2_rn(d[0],d[1]), p1=__floats2half2_rn(d[2],d[3]);
        *reinterpret_cast<unsigned*>(o16+row*DM+col)=*reinterpret_cast<unsigned*>(&p0);
        *reinterpret_cast<unsigned*>(o16+(row+8)*DM+col)=*reinterpret_cast<unsigned*>(&p1);
    }
}

extern "C" void kernel_launch(void* const* d_in, const int* in_sizes, int n_in,
                              void* d_out, int out_size)
{
    const float* x =(const float*)d_in[0];
    const float* Wq=(const float*)d_in[1];
    const float* Wk=(const float*)d_in[2];
    const float* bk=(const float*)d_in[3];
    const float* Wv=(const float*)d_in[4];
    const float* bv=(const float*)d_in[5];
    const float* gq=(const float*)d_in[6];
    const float* gk=(const float*)d_in[7];
    const float* Wo=(const float*)d_in[8];
    const float* bo=(const float*)d_in[9];
    float* out=(float*)d_out;

    f16 *x16,*w16,*q16,*k16,*vt,*o16;
    float *qkv,*biasqkv,*rsum;
    cudaGetSymbolAddress((void**)&x16,g_x16); cudaGetSymbolAddress((void**)&w16,g_w16);
    cudaGetSymbolAddress((void**)&qkv,g_qkv); cudaGetSymbolAddress((void**)&biasqkv,g_biasqkv);
    cudaGetSymbolAddress((void**)&q16,g_q16); cudaGetSymbolAddress((void**)&k16,g_k16);
    cudaGetSymbolAddress((void**)&vt,g_vt);
    cudaGetSymbolAddress((void**)&rsum,g_rsum);
    cudaGetSymbolAddress((void**)&o16,g_o16);

    cudaFuncSetAttribute(gemm_h,    cudaFuncAttributeMaxDynamicSharedMemorySize, 65536);
    cudaFuncSetAttribute(colsum_h,  cudaFuncAttributeMaxDynamicSharedMemorySize, 49152);
    cudaFuncSetAttribute(flashpv_h, cudaFuncAttributeMaxDynamicSharedMemorySize, 49152);

    const long NX=(long)ROWS*DM;
    // prep: all conversions + bias concat
    prep<<<dim3((unsigned)((NX/4+255)/256), 5),256>>>(x, Wq, Wk, Wv, Wo, bk, bv, x16, w16, biasqkv);

    // fused QKV projection: qkv[8192][2304] = x @ [Wq;Wk;Wv]^T + biasqkv
    gemm_h<<<dim3(NQKV/128, ROWS/128),256,65536>>>(x16, w16, biasqkv, nullptr, qkv, DM, NQKV);

    // LN for q (scale folded) and k in one launch
    ln2f16<<<dim3(ROWS,2),256>>>(qkv, gq, gk, q16, k16);

    colsum_h<<<dim3(SEQ/128, ZBN),256,49152>>>(q16, k16, rsum);
    vtscale<<<dim3(SEQ/32, DM/32, 4), dim3(32,8)>>>(qkv, rsum, vt);
    flashpv_h<<<dim3(SEQ/128, ZBN),256,49152>>>(q16, k16, vt, o16);

    // out = O @ Wo^T + bo + x
    gemm_h<<<dim3(DM/128, ROWS/128),256,65536>>>(o16, w16+3*(long)DM*DM, bo, x, out, DM, DM);
}